// round 5
// baseline (speedup 1.0000x reference)
#include <cuda_runtime.h>
#include <math.h>
#include <stdint.h>

#define BB 4
#define TT 1024
#define DD 1024
#define NN 16
#define MM (BB*TT)   // 4096

// int8 GEMM tiling
#define GBM 128
#define GBN 128
#define GBK 32
#define ROWB 48                  // 32B data + 16B pad, conflict-free
#define ATILE (128*ROWB)         // 6144 per digit tile
#define STAGE_B (4*ATILE)        // 24576: [A1|A2|B1|B2]
#define NPIPE 4
#define GEMM_SMEM (NPIPE*STAGE_B) // 98304
#define NSTAGE (DD/GBK)          // 32
#define QSCALE 16256.0f          // 127*128

// ---------------- scratch ----------------
__device__ __align__(256) float g_x1[MM*DD];
__device__ __align__(256) float g_z [MM*DD];
__device__ __align__(256) float g_x3[MM*DD];
__device__ __align__(256) float g_dt[MM*DD];
__device__ __align__(256) float g_y [MM*DD];
__device__ __align__(256) float g_Bm[MM*NN];
__device__ __align__(256) float g_Cm[MM*NN];

__device__ __align__(256) int8_t g_ud1[MM*DD],  g_ud2[MM*DD];
__device__ __align__(256) int8_t g_xd1[MM*DD],  g_xd2[MM*DD];
__device__ __align__(256) int8_t g_yd1[MM*DD],  g_yd2[MM*DD];
__device__ __align__(256) int8_t g_w0d1[DD*DD], g_w0d2[DD*DD];  // Win^T
__device__ __align__(256) int8_t g_w1d1[DD*DD], g_w1d2[DD*DD];  // Wg^T
__device__ __align__(256) int8_t g_w2d1[DD*DD], g_w2d2[DD*DD];  // Wdt^T
__device__ __align__(256) int8_t g_w3d1[DD*DD], g_w3d2[DD*DD];  // Wout^T
__device__ __align__(256) float g_fsu[MM], g_fsx[MM], g_fsy[MM];
__device__ __align__(256) float g_fsw[4*DD];

__device__ __forceinline__ float silu_f(float v) { return v / (1.f + __expf(-v)); }
__device__ __forceinline__ float softplus_f(float v) { return (v > 20.f) ? v : log1pf(__expf(v)); }

__device__ __forceinline__ uint32_t smem_to_u32(const void* p) {
    uint32_t a;
    asm("{ .reg .u64 t; cvta.to.shared.u64 t, %1; cvt.u32.u64 %0, t; }" : "=r"(a) : "l"(p));
    return a;
}
__device__ __forceinline__ void cpa16(uint32_t s, const void* g) {
    asm volatile("cp.async.cg.shared.global [%0], [%1], 16;\n" :: "r"(s), "l"(g));
}
__device__ __forceinline__ void cp_commit() { asm volatile("cp.async.commit_group;\n" ::: "memory"); }
template<int N> __device__ __forceinline__ void cp_wait() { asm volatile("cp.async.wait_group %0;\n" :: "n"(N) : "memory"); }

__device__ __forceinline__ void ldsm_x4(uint32_t* r, uint32_t addr) {
    asm volatile("ldmatrix.sync.aligned.m8n8.x4.shared.b16 {%0,%1,%2,%3}, [%4];"
        : "=r"(r[0]), "=r"(r[1]), "=r"(r[2]), "=r"(r[3]) : "r"(addr));
}
__device__ __forceinline__ void ldsm_x2(uint32_t* r, uint32_t addr) {
    asm volatile("ldmatrix.sync.aligned.m8n8.x2.shared.b16 {%0,%1}, [%2];"
        : "=r"(r[0]), "=r"(r[1]) : "r"(addr));
}
__device__ __forceinline__ void imma(int* c, const uint32_t* a, const uint32_t* b) {
    asm volatile("mma.sync.aligned.m16n8k32.row.col.s32.s8.s8.s32 "
        "{%0,%1,%2,%3}, {%4,%5,%6,%7}, {%8,%9}, {%0,%1,%2,%3};"
        : "+r"(c[0]), "+r"(c[1]), "+r"(c[2]), "+r"(c[3])
        : "r"(a[0]), "r"(a[1]), "r"(a[2]), "r"(a[3]), "r"(b[0]), "r"(b[1]));
}

// quantize one fp32 value given inv = QSCALE / rowmax
__device__ __forceinline__ void quant2(float x, float inv, int& d1, int& d2) {
    int t = __float2int_rn(x * inv);
    t = max(min(t, 16256), -16256);
    d1 = (t + 64) >> 7;
    d2 = t - (d1 << 7);
}

// ---------------- int8 2-digit GEMM: C = A @ W^T (+bias, act) ----------------
// A digits [M,K] row-major, W digits [N,K] row-major. MODE 0:none 1:silu 2:softplus
template<int MODE>
__global__ __launch_bounds__(512, 1)
void gemm_q(const int8_t* __restrict__ Ad1, const int8_t* __restrict__ Ad2,
            const float* __restrict__ fa,
            const int8_t* __restrict__ Bd1, const int8_t* __restrict__ Bd2,
            const float* __restrict__ fb,
            const float* __restrict__ bias, float* __restrict__ C)
{
    extern __shared__ char smem[];
    const uint32_t sb = smem_to_u32(smem);
    const int tid = threadIdx.x;
    const int lane = tid & 31;
    const int wid = tid >> 5;        // 0..15
    const int wm = wid & 3;          // 4 warps in M
    const int wn = wid >> 2;         // 4 warps in N
    const int bn = blockIdx.x, bm = blockIdx.y;

    int acc1[2][4][4], accm[2][4][4];
#pragma unroll
    for (int i = 0; i < 2; i++)
#pragma unroll
        for (int j = 0; j < 4; j++)
#pragma unroll
            for (int k = 0; k < 4; k++) { acc1[i][j][k] = 0; accm[i][j][k] = 0; }

    // loader: tid<256 -> A digits, else B digits; (row, 16B-half)
    const int lr = (tid & 255) >> 1;
    const int lch = tid & 1;
    const bool isB = tid >= 256;
    const int8_t* g1 = isB ? (Bd1 + (size_t)(bn * GBN + lr) * DD) : (Ad1 + (size_t)(bm * GBM + lr) * DD);
    const int8_t* g2 = isB ? (Bd2 + (size_t)(bn * GBN + lr) * DD) : (Ad2 + (size_t)(bm * GBM + lr) * DD);
    const uint32_t so1 = (isB ? 2u * ATILE : 0u) + (uint32_t)lr * ROWB + (uint32_t)lch * 16;

    auto load_stage = [&](int buf, int s) {
        const uint32_t st = sb + (uint32_t)buf * STAGE_B;
        const size_t k0 = (size_t)s * GBK + (size_t)lch * 16;
        cpa16(st + so1,         g1 + k0);
        cpa16(st + so1 + ATILE, g2 + k0);
        cp_commit();
    };

    load_stage(0, 0);
    load_stage(1, 1);
    load_stage(2, 2);

    const uint32_t a_off = (uint32_t)(wm * 32 + (lane & 15)) * ROWB + ((lane >> 4) * 16);
    const uint32_t b_off = 2u * ATILE + (uint32_t)(wn * 32 + (lane & 7)) * ROWB + (((lane >> 3) & 1) * 16);

    for (int s = 0; s < NSTAGE; s++) {
        const int buf = s & (NPIPE - 1);
        if (s < NSTAGE - 2)       cp_wait<2>();
        else if (s == NSTAGE - 2) cp_wait<1>();
        else                      cp_wait<0>();
        __syncthreads();

        const uint32_t st = sb + (uint32_t)buf * STAGE_B;
        uint32_t b1f[4][2], b2f[4][2];
#pragma unroll
        for (int nt = 0; nt < 4; nt++) {
            uint32_t ad = st + b_off + (uint32_t)nt * (8 * ROWB);
            ldsm_x2(b1f[nt], ad);
            ldsm_x2(b2f[nt], ad + ATILE);
        }
#pragma unroll
        for (int mt = 0; mt < 2; mt++) {
            uint32_t ad = st + a_off + (uint32_t)mt * (16 * ROWB);
            uint32_t a1f[4], a2f[4];
            ldsm_x4(a1f, ad);
            ldsm_x4(a2f, ad + ATILE);
#pragma unroll
            for (int nt = 0; nt < 4; nt++) {
                imma(acc1[mt][nt], a1f, b1f[nt]);
                imma(accm[mt][nt], a1f, b2f[nt]);
                imma(accm[mt][nt], a2f, b1f[nt]);
            }
        }

        if (s + NPIPE - 1 < NSTAGE) load_stage((s + NPIPE - 1) & (NPIPE - 1), s + NPIPE - 1);
    }

    // epilogue: C[m,n] = fa[m]*fb[n]*(16384*D11 + 128*Dmid) + bias
    const int row0 = bm * GBM + wm * 32 + (lane >> 2);
    const int col0 = bn * GBN + wn * 32 + (lane & 3) * 2;
#pragma unroll
    for (int nt = 0; nt < 4; nt++) {
        const int col = col0 + nt * 8;
        const float fb0 = fb[col], fb1 = fb[col + 1];
        const float bi0 = bias[col], bi1 = bias[col + 1];
#pragma unroll
        for (int mt = 0; mt < 2; mt++) {
#pragma unroll
            for (int half = 0; half < 2; half++) {
                const int row = row0 + mt * 16 + half * 8;
                const float far = fa[row];
                float v0 = far * fb0 * (16384.f * (float)acc1[mt][nt][half * 2 + 0]
                                        + 128.f * (float)accm[mt][nt][half * 2 + 0]) + bi0;
                float v1 = far * fb1 * (16384.f * (float)acc1[mt][nt][half * 2 + 1]
                                        + 128.f * (float)accm[mt][nt][half * 2 + 1]) + bi1;
                if (MODE == 1) { v0 = silu_f(v0); v1 = silu_f(v1); }
                else if (MODE == 2) { v0 = softplus_f(v0); v1 = softplus_f(v1); }
                float2 w; w.x = v0; w.y = v1;
                *(float2*)(C + (size_t)row * DD + col) = w;
            }
        }
    }
}

// ---------------- row quantize: fp32 row -> int8 digits + scale ----------------
__global__ __launch_bounds__(256)
void qact_kernel(const float* __restrict__ X, int8_t* __restrict__ D1,
                 int8_t* __restrict__ D2, float* __restrict__ fs)
{
    __shared__ float red[8];
    const int row = blockIdx.x;
    const int tid = threadIdx.x;
    float4 v = *(const float4*)(X + (size_t)row * DD + tid * 4);
    float m = fmaxf(fmaxf(fabsf(v.x), fabsf(v.y)), fmaxf(fabsf(v.z), fabsf(v.w)));
#pragma unroll
    for (int o = 16; o > 0; o >>= 1) m = fmaxf(m, __shfl_xor_sync(0xffffffffu, m, o));
    if ((tid & 31) == 0) red[tid >> 5] = m;
    __syncthreads();
    float S = fmaxf(fmaxf(fmaxf(red[0], red[1]), fmaxf(red[2], red[3])),
                    fmaxf(fmaxf(red[4], red[5]), fmaxf(red[6], red[7])));
    const float inv = (S > 1e-30f) ? QSCALE / S : 0.f;
    int d10, d20, d11, d21, d12, d22, d13, d23;
    quant2(v.x, inv, d10, d20); quant2(v.y, inv, d11, d21);
    quant2(v.z, inv, d12, d22); quant2(v.w, inv, d13, d23);
    uint32_t p1 = (d10 & 255) | ((d11 & 255) << 8) | ((d12 & 255) << 16) | ((d13 & 255) << 24);
    uint32_t p2 = (d20 & 255) | ((d21 & 255) << 8) | ((d22 & 255) << 16) | ((d23 & 255) << 24);
    *(uint32_t*)(D1 + (size_t)row * DD + tid * 4) = p1;
    *(uint32_t*)(D2 + (size_t)row * DD + tid * 4) = p2;
    if (tid == 0) fs[row] = S * (1.f / QSCALE);
}

// ---------------- conv3 + silu + fp32 out + row quantize ----------------
__global__ __launch_bounds__(256)
void conv_rowq_kernel(const float* __restrict__ x1, const float* __restrict__ w,
                      const float* __restrict__ cb, float* __restrict__ x3,
                      int8_t* __restrict__ D1, int8_t* __restrict__ D2,
                      float* __restrict__ fs)
{
    __shared__ float red[8];
    const int row = blockIdx.x;
    const int t = row & (TT - 1);
    const int tid = threadIdx.x;
    const int d = tid * 4;
    const float* xc = x1 + (size_t)row * DD;

    float4 vc = *(const float4*)(xc + d);
    float r0[4];
    float w1a[4], w0a[4], w2a[4], cba[4];
#pragma unroll
    for (int j = 0; j < 4; j++) {
        w0a[j] = w[(d + j) * 3 + 0];
        w1a[j] = w[(d + j) * 3 + 1];
        w2a[j] = w[(d + j) * 3 + 2];
        cba[j] = cb[d + j];
    }
    float cv[4] = { vc.x * w1a[0] + cba[0], vc.y * w1a[1] + cba[1],
                    vc.z * w1a[2] + cba[2], vc.w * w1a[3] + cba[3] };
    if (t > 0) {
        float4 vm = *(const float4*)(xc - DD + d);
        cv[0] = fmaf(vm.x, w0a[0], cv[0]); cv[1] = fmaf(vm.y, w0a[1], cv[1]);
        cv[2] = fmaf(vm.z, w0a[2], cv[2]); cv[3] = fmaf(vm.w, w0a[3], cv[3]);
    }
    if (t < TT - 1) {
        float4 vp = *(const float4*)(xc + DD + d);
        cv[0] = fmaf(vp.x, w2a[0], cv[0]); cv[1] = fmaf(vp.y, w2a[1], cv[1]);
        cv[2] = fmaf(vp.z, w2a[2], cv[2]); cv[3] = fmaf(vp.w, w2a[3], cv[3]);
    }
#pragma unroll
    for (int j = 0; j < 4; j++) r0[j] = silu_f(cv[j]);
    float4 out4; out4.x = r0[0]; out4.y = r0[1]; out4.z = r0[2]; out4.w = r0[3];
    *(float4*)(x3 + (size_t)row * DD + d) = out4;

    float m = fmaxf(fmaxf(fabsf(r0[0]), fabsf(r0[1])), fmaxf(fabsf(r0[2]), fabsf(r0[3])));
#pragma unroll
    for (int o = 16; o > 0; o >>= 1) m = fmaxf(m, __shfl_xor_sync(0xffffffffu, m, o));
    if ((tid & 31) == 0) red[tid >> 5] = m;
    __syncthreads();
    float S = fmaxf(fmaxf(fmaxf(red[0], red[1]), fmaxf(red[2], red[3])),
                    fmaxf(fmaxf(red[4], red[5]), fmaxf(red[6], red[7])));
    const float inv = (S > 1e-30f) ? QSCALE / S : 0.f;
    int d1[4], d2[4];
#pragma unroll
    for (int j = 0; j < 4; j++) quant2(r0[j], inv, d1[j], d2[j]);
    uint32_t p1 = (d1[0] & 255) | ((d1[1] & 255) << 8) | ((d1[2] & 255) << 16) | ((d1[3] & 255) << 24);
    uint32_t p2 = (d2[0] & 255) | ((d2[1] & 255) << 8) | ((d2[2] & 255) << 16) | ((d2[3] & 255) << 24);
    *(uint32_t*)(D1 + (size_t)row * DD + d) = p1;
    *(uint32_t*)(D2 + (size_t)row * DD + d) = p2;
    if (tid == 0) fs[row] = S * (1.f / QSCALE);
}

// ---------------- weight column max (per output-n scale) ----------------
__global__ __launch_bounds__(256)
void wcolmax_kernel(const float* W0, const float* W1, const float* W2, const float* W3,
                    float* __restrict__ fsw)
{
    __shared__ float red[256];
    const int wi = blockIdx.y;
    const float* W = (wi == 0) ? W0 : (wi == 1) ? W1 : (wi == 2) ? W2 : W3;
    const int col = blockIdx.x * 128 + (threadIdx.x & 127);
    const int kh = threadIdx.x >> 7;
    float m = 0.f;
    for (int k = kh * 512; k < kh * 512 + 512; k++)
        m = fmaxf(m, fabsf(W[(size_t)k * DD + col]));
    red[threadIdx.x] = m;
    __syncthreads();
    if (threadIdx.x < 128) {
        float S = fmaxf(red[threadIdx.x], red[threadIdx.x + 128]);
        fsw[wi * DD + col] = S * (1.f / QSCALE);
    }
}

// ---------------- weight transpose + quantize ----------------
__global__ __launch_bounds__(256)
void wquant_kernel(const float* W0, const float* W1, const float* W2, const float* W3,
                   const float* __restrict__ fsw,
                   int8_t* D10, int8_t* D20, int8_t* D11, int8_t* D21,
                   int8_t* D12, int8_t* D22, int8_t* D13, int8_t* D23)
{
    __shared__ float s[32][33];
    const int wi = blockIdx.z;
    const float* W = (wi == 0) ? W0 : (wi == 1) ? W1 : (wi == 2) ? W2 : W3;
    int8_t* T1 = (wi == 0) ? D10 : (wi == 1) ? D11 : (wi == 2) ? D12 : D13;
    int8_t* T2 = (wi == 0) ? D20 : (wi == 1) ? D21 : (wi == 2) ? D22 : D23;
    const int bx = blockIdx.x * 32, by = blockIdx.y * 32;
    const int tx = threadIdx.x, ty = threadIdx.y;
#pragma unroll
    for (int j = ty; j < 32; j += 8)
        s[j][tx] = W[(size_t)(by + j) * DD + bx + tx];
    __syncthreads();
#pragma unroll
    for (int j = ty; j < 32; j += 8) {
        const int n = bx + j;
        const float fv = fsw[wi * DD + n];
        const float inv = (fv > 1e-38f) ? 1.f / fv : 0.f;
        int d1, d2;
        quant2(s[tx][j], inv, d1, d2);
        T1[(size_t)n * DD + by + tx] = (int8_t)d1;
        T2[(size_t)n * DD + by + tx] = (int8_t)d2;
    }
}

// ---------------- B/C projections ----------------
__global__ __launch_bounds__(256)
void proj_bc_kernel(const float* __restrict__ X,
                    const float* __restrict__ Wb, const float* __restrict__ Wc,
                    const float* __restrict__ bb, const float* __restrict__ bc,
                    float* __restrict__ Bm, float* __restrict__ Cm)
{
    __shared__ float Xs[32][33];
    __shared__ float Ws[32][32];
    const int tid = threadIdx.x;
    const int row0 = blockIdx.x * 32;
    const int c = tid & 31;
    const int rq = tid >> 5;
    float acc[4] = {0.f, 0.f, 0.f, 0.f};
    const int lr = tid / 8;
    const int lc = (tid % 8) * 4;

    for (int k0 = 0; k0 < DD; k0 += 32) {
        float4 xv = *(const float4*)(X + (size_t)(row0 + lr) * DD + k0 + lc);
        Xs[lr][lc + 0] = xv.x; Xs[lr][lc + 1] = xv.y;
        Xs[lr][lc + 2] = xv.z; Xs[lr][lc + 3] = xv.w;
#pragma unroll
        for (int q = 0; q < 4; q++) {
            int cc = lc + q;
            float wv = (cc < 16) ? Wb[(size_t)(k0 + lr) * 16 + cc]
                                 : Wc[(size_t)(k0 + lr) * 16 + cc - 16];
            Ws[lr][cc] = wv;
        }
        __syncthreads();
#pragma unroll
        for (int kk = 0; kk < 32; kk++) {
            float w = Ws[kk][c];
#pragma unroll
            for (int r = 0; r < 4; r++)
                acc[r] = fmaf(Xs[rq * 4 + r][kk], w, acc[r]);
        }
        __syncthreads();
    }
#pragma unroll
    for (int r = 0; r < 4; r++) {
        int row = row0 + rq * 4 + r;
        if (c < 16) Bm[(size_t)row * 16 + c]      = acc[r] + bb[c];
        else        Cm[(size_t)row * 16 + c - 16] = acc[r] + bc[c - 16];
    }
}

// ---------------- selective scan (fp32 out) ----------------
#define SCHUNK 32
__global__ __launch_bounds__(128)
void scan_kernel(const float* __restrict__ dt, const float* __restrict__ x,
                 const float* __restrict__ Bm, const float* __restrict__ Cm,
                 const float* __restrict__ A,  const float* __restrict__ z,
                 float* __restrict__ g)
{
    const int blk = blockIdx.x;
    const int b = blk >> 7;
    const int d0 = (blk & 127) * 8;
    const int tid = threadIdx.x;
    const int n = tid & 15;
    const int dl = tid >> 4;
    const int d = d0 + dl;

    const float a = A[(size_t)d * NN + n];
    float h = 0.f;

    __shared__ float s_dt[SCHUNK][8], s_x[SCHUNK][8], s_z[SCHUNK][8];
    __shared__ float s_B[SCHUNK][16], s_C[SCHUNK][16];
    __shared__ float s_y[SCHUNK][8];

    const size_t base = (size_t)b * TT * DD;
    const int li = tid / 4;
    const int lj2 = (tid % 4) * 2;
    const int lj4 = (tid % 4) * 4;

    for (int t0 = 0; t0 < TT; t0 += SCHUNK) {
        size_t rbase = base + (size_t)(t0 + li) * DD + d0;
        *(float2*)&s_dt[li][lj2] = *(const float2*)(dt + rbase + lj2);
        *(float2*)&s_x [li][lj2] = *(const float2*)(x  + rbase + lj2);
        *(float2*)&s_z [li][lj2] = *(const float2*)(z  + rbase + lj2);
        size_t nbase = ((size_t)b * TT + t0 + li) * NN;
        *(float4*)&s_B[li][lj4] = *(const float4*)(Bm + nbase + lj4);
        *(float4*)&s_C[li][lj4] = *(const float4*)(Cm + nbase + lj4);
        __syncthreads();

#pragma unroll 8
        for (int i = 0; i < SCHUNK; i++) {
            float dtv = s_dt[i][dl];
            float xv  = s_x[i][dl];
            float Bv  = s_B[i][n];
            float Cv  = s_C[i][n];
            float da  = __expf(dtv * a);
            h = fmaf(da, h, dtv * Bv * xv);
            float p = h * Cv;
            p += __shfl_xor_sync(0xffffffffu, p, 1);
            p += __shfl_xor_sync(0xffffffffu, p, 2);
            p += __shfl_xor_sync(0xffffffffu, p, 4);
            p += __shfl_xor_sync(0xffffffffu, p, 8);
            if (n == 0) s_y[i][dl] = p * s_z[i][dl];
        }
        __syncthreads();

        *(float2*)(g + rbase + lj2) = *(float2*)&s_y[li][lj2];
        __syncthreads();
    }
}

// ---------------- launch ----------------
extern "C" void kernel_launch(void* const* d_in, const int* in_sizes, int n_in,
                              void* d_out, int out_size)
{
    const float* u    = (const float*)d_in[0];
    const float* Win  = (const float*)d_in[1];
    const float* b_in = (const float*)d_in[2];
    const float* Wg   = (const float*)d_in[3];
    const float* bg   = (const float*)d_in[4];
    const float* Wout = (const float*)d_in[5];
    const float* bout = (const float*)d_in[6];
    const float* convw= (const float*)d_in[7];
    const float* convb= (const float*)d_in[8];
    const float* A    = (const float*)d_in[9];
    const float* Wb   = (const float*)d_in[10];
    const float* bb   = (const float*)d_in[11];
    const float* Wc   = (const float*)d_in[12];
    const float* bc   = (const float*)d_in[13];
    const float* Wdt  = (const float*)d_in[14];
    const float* bdt  = (const float*)d_in[15];
    float* out = (float*)d_out;

    float *x1, *zb, *x3, *dtb, *yb, *Bmb, *Cmb;
    cudaGetSymbolAddress((void**)&x1,  g_x1);
    cudaGetSymbolAddress((void**)&zb,  g_z);
    cudaGetSymbolAddress((void**)&x3,  g_x3);
    cudaGetSymbolAddress((void**)&dtb, g_dt);
    cudaGetSymbolAddress((void**)&yb,  g_y);
    cudaGetSymbolAddress((void**)&Bmb, g_Bm);
    cudaGetSymbolAddress((void**)&Cmb, g_Cm);

    int8_t *ud1, *ud2, *xd1, *xd2, *yd1, *yd2;
    int8_t *w0d1, *w0d2, *w1d1, *w1d2, *w2d1, *w2d2, *w3d1, *w3d2;
    float *fsu, *fsx, *fsy, *fsw;
    cudaGetSymbolAddress((void**)&ud1, g_ud1);  cudaGetSymbolAddress((void**)&ud2, g_ud2);
    cudaGetSymbolAddress((void**)&xd1, g_xd1);  cudaGetSymbolAddress((void**)&xd2, g_xd2);
    cudaGetSymbolAddress((void**)&yd1, g_yd1);  cudaGetSymbolAddress((void**)&yd2, g_yd2);
    cudaGetSymbolAddress((void**)&w0d1, g_w0d1); cudaGetSymbolAddress((void**)&w0d2, g_w0d2);
    cudaGetSymbolAddress((void**)&w1d1, g_w1d1); cudaGetSymbolAddress((void**)&w1d2, g_w1d2);
    cudaGetSymbolAddress((void**)&w2d1, g_w2d1); cudaGetSymbolAddress((void**)&w2d2, g_w2d2);
    cudaGetSymbolAddress((void**)&w3d1, g_w3d1); cudaGetSymbolAddress((void**)&w3d2, g_w3d2);
    cudaGetSymbolAddress((void**)&fsu, g_fsu);  cudaGetSymbolAddress((void**)&fsx, g_fsx);
    cudaGetSymbolAddress((void**)&fsy, g_fsy);  cudaGetSymbolAddress((void**)&fsw, g_fsw);

    cudaFuncSetAttribute((const void*)gemm_q<0>, cudaFuncAttributeMaxDynamicSharedMemorySize, GEMM_SMEM);
    cudaFuncSetAttribute((const void*)gemm_q<1>, cudaFuncAttributeMaxDynamicSharedMemorySize, GEMM_SMEM);
    cudaFuncSetAttribute((const void*)gemm_q<2>, cudaFuncAttributeMaxDynamicSharedMemorySize, GEMM_SMEM);

    // weight prep
    wcolmax_kernel<<<dim3(8, 4), 256>>>(Win, Wg, Wdt, Wout, fsw);
    wquant_kernel<<<dim3(32, 32, 4), dim3(32, 8)>>>(Win, Wg, Wdt, Wout, fsw,
        w0d1, w0d2, w1d1, w1d2, w2d1, w2d2, w3d1, w3d2);
    qact_kernel<<<MM, 256>>>(u, ud1, ud2, fsu);

    dim3 gg(DD / GBN, MM / GBM);  // (8, 32)
    gemm_q<0><<<gg, 512, GEMM_SMEM>>>(ud1, ud2, fsu, w0d1, w0d2, fsw + 0 * DD, b_in, x1);
    gemm_q<1><<<gg, 512, GEMM_SMEM>>>(ud1, ud2, fsu, w1d1, w1d2, fsw + 1 * DD, bg, zb);
    conv_rowq_kernel<<<MM, 256>>>(x1, convw, convb, x3, xd1, xd2, fsx);
    gemm_q<2><<<gg, 512, GEMM_SMEM>>>(xd1, xd2, fsx, w2d1, w2d2, fsw + 2 * DD, bdt, dtb);
    proj_bc_kernel<<<MM / 32, 256>>>(x3, Wb, Wc, bb, bc, Bmb, Cmb);
    scan_kernel<<<BB * (DD / 8), 128>>>(dtb, x3, Bmb, Cmb, A, zb, yb);
    qact_kernel<<<MM, 256>>>(yb, yd1, yd2, fsy);
    gemm_q<0><<<gg, 512, GEMM_SMEM>>>(yd1, yd2, fsy, w3d1, w3d2, fsw + 3 * DD, bout, out);
}

// round 6
// speedup vs baseline: 1.9664x; 1.9664x over previous
#include <cuda_runtime.h>
#include <cuda_bf16.h>
#include <math.h>
#include <stdint.h>

#define BB 4
#define TT 1024
#define DD 1024
#define NN 16
#define MM (BB*TT)   // 4096

// GEMM tiling (mma.sync path)
#define Bb16 __nv_bfloat16
#define GBM 128
#define GBN 128
#define GBK 16
#define ROWB 48                 // padded row bytes: 16*2 + 16 (conflict-free 48B stride)
#define TILE_B (128*ROWB)       // 6144
#define OFF_AH 0
#define OFF_AL (TILE_B)
#define OFF_BH (2*TILE_B)
#define OFF_BL (3*TILE_B)
#define STAGE_B (4*TILE_B)      // 24576
#define NPIPE 4
#define GEMM_SMEM (NPIPE*STAGE_B)   // 98304
#define NSTAGE (DD/GBK)         // 64

// ---------------- scratch (no allocations allowed) ----------------
__device__ __align__(256) float g_x1[MM*DD];
__device__ __align__(256) float g_z [MM*DD];
__device__ __align__(256) float g_x3[MM*DD];
__device__ __align__(256) float g_dt[MM*DD];
__device__ __align__(256) float g_Bm[MM*NN];
__device__ __align__(256) float g_Cm[MM*NN];

__device__ __align__(256) Bb16 g_uh[MM*DD],  g_ul[MM*DD];
__device__ __align__(256) Bb16 g_x3h[MM*DD], g_x3l[MM*DD];
__device__ __align__(256) Bb16 g_yh[MM*DD],  g_yl[MM*DD];
__device__ __align__(256) Bb16 g_Wint_h[DD*DD], g_Wint_l[DD*DD];
__device__ __align__(256) Bb16 g_Wgt_h [DD*DD], g_Wgt_l [DD*DD];
__device__ __align__(256) Bb16 g_Wdtt_h[DD*DD], g_Wdtt_l[DD*DD];
__device__ __align__(256) Bb16 g_Wot_h [DD*DD], g_Wot_l [DD*DD];

__device__ __forceinline__ float silu_f(float v) { return v / (1.f + __expf(-v)); }
__device__ __forceinline__ float softplus_f(float v) { return (v > 20.f) ? v : log1pf(__expf(v)); }

__device__ __forceinline__ uint32_t smem_to_u32(const void* p) {
    uint32_t a;
    asm("{ .reg .u64 t; cvta.to.shared.u64 t, %1; cvt.u32.u64 %0, t; }" : "=r"(a) : "l"(p));
    return a;
}
__device__ __forceinline__ void cpa16(uint32_t s, const void* g) {
    asm volatile("cp.async.cg.shared.global [%0], [%1], 16;\n" :: "r"(s), "l"(g));
}
__device__ __forceinline__ void cp_commit() { asm volatile("cp.async.commit_group;\n" ::: "memory"); }
template<int N> __device__ __forceinline__ void cp_wait() { asm volatile("cp.async.wait_group %0;\n" :: "n"(N) : "memory"); }

__device__ __forceinline__ void ldsm_x4(uint32_t* r, uint32_t addr) {
    asm volatile("ldmatrix.sync.aligned.m8n8.x4.shared.b16 {%0,%1,%2,%3}, [%4];"
        : "=r"(r[0]), "=r"(r[1]), "=r"(r[2]), "=r"(r[3]) : "r"(addr));
}
__device__ __forceinline__ void ldsm_x2(uint32_t* r, uint32_t addr) {
    asm volatile("ldmatrix.sync.aligned.m8n8.x2.shared.b16 {%0,%1}, [%2];"
        : "=r"(r[0]), "=r"(r[1]) : "r"(addr));
}
__device__ __forceinline__ void mma16816(float* c, const uint32_t* a, const uint32_t* b) {
    asm volatile("mma.sync.aligned.m16n8k16.row.col.f32.bf16.bf16.f32 "
        "{%0,%1,%2,%3}, {%4,%5,%6,%7}, {%8,%9}, {%0,%1,%2,%3};"
        : "+f"(c[0]), "+f"(c[1]), "+f"(c[2]), "+f"(c[3])
        : "r"(a[0]), "r"(a[1]), "r"(a[2]), "r"(a[3]), "r"(b[0]), "r"(b[1]));
}

__device__ __forceinline__ void split2(float v, Bb16& h, Bb16& l) {
    h = __float2bfloat16(v);
    l = __float2bfloat16(v - __bfloat162float(h));
}

// ---------------- 3x-bf16 GEMM via mma.sync, 4-stage cp.async pipeline ----------------
template<int MODE>
__global__ __launch_bounds__(256, 2)
void gemm_mma(const Bb16* __restrict__ Ah, const Bb16* __restrict__ Al,
              const Bb16* __restrict__ Bh, const Bb16* __restrict__ Bl,
              const float* __restrict__ bias, float* __restrict__ C)
{
    extern __shared__ char smem[];
    const uint32_t sb = smem_to_u32(smem);
    const int tid = threadIdx.x;
    const int lane = tid & 31;
    const int wid = tid >> 5;
    const int wm = wid & 1;          // 2 warps in M
    const int wn = wid >> 1;         // 4 warps in N
    const int bn = blockIdx.x, bm = blockIdx.y;

    float acc[4][4][4];
#pragma unroll
    for (int i = 0; i < 4; i++)
#pragma unroll
        for (int j = 0; j < 4; j++)
#pragma unroll
            for (int k = 0; k < 4; k++) acc[i][j][k] = 0.f;

    const int lrow = tid >> 1;
    const int lch  = tid & 1;

    const Bb16* gAh = Ah + (size_t)(bm * GBM + lrow) * DD + lch * 8;
    const Bb16* gAl = Al + (size_t)(bm * GBM + lrow) * DD + lch * 8;
    const Bb16* gBh = Bh + (size_t)(bn * GBN + lrow) * DD + lch * 8;
    const Bb16* gBl = Bl + (size_t)(bn * GBN + lrow) * DD + lch * 8;
    const uint32_t srow = (uint32_t)lrow * ROWB + (uint32_t)lch * 16;

    auto load_stage = [&](int buf, int s) {
        const uint32_t st = sb + (uint32_t)buf * STAGE_B;
        const size_t k0 = (size_t)s * GBK;
        cpa16(st + OFF_AH + srow, gAh + k0);
        cpa16(st + OFF_AL + srow, gAl + k0);
        cpa16(st + OFF_BH + srow, gBh + k0);
        cpa16(st + OFF_BL + srow, gBl + k0);
        cp_commit();
    };

    load_stage(0, 0);
    load_stage(1, 1);
    load_stage(2, 2);

    const uint32_t a_off = (uint32_t)(wm * 64 + (lane & 15)) * ROWB + ((lane >> 4) * 16);
    const uint32_t b_off = (uint32_t)(wn * 32 + (lane & 7)) * ROWB + (((lane >> 3) & 1) * 16);

    for (int s = 0; s < NSTAGE; s++) {
        const int buf = s & (NPIPE - 1);
        if (s < NSTAGE - 2)       cp_wait<2>();
        else if (s == NSTAGE - 2) cp_wait<1>();
        else                      cp_wait<0>();
        __syncthreads();

        const uint32_t st = sb + (uint32_t)buf * STAGE_B;
        uint32_t bhf[4][2], blf[4][2];
#pragma unroll
        for (int nt = 0; nt < 4; nt++) {
            uint32_t ad = st + OFF_BH + b_off + (uint32_t)nt * (8 * ROWB);
            ldsm_x2(bhf[nt], ad);
            ldsm_x2(blf[nt], ad + (OFF_BL - OFF_BH));
        }
#pragma unroll
        for (int mt = 0; mt < 4; mt++) {
            uint32_t ad = st + OFF_AH + a_off + (uint32_t)mt * (16 * ROWB);
            uint32_t ahf[4], alf[4];
            ldsm_x4(ahf, ad);
            ldsm_x4(alf, ad + (OFF_AL - OFF_AH));
#pragma unroll
            for (int nt = 0; nt < 4; nt++) {
                mma16816(acc[mt][nt], ahf, bhf[nt]);
                mma16816(acc[mt][nt], ahf, blf[nt]);
                mma16816(acc[mt][nt], alf, bhf[nt]);
            }
        }

        if (s + NPIPE - 1 < NSTAGE) load_stage((s + NPIPE - 1) & (NPIPE - 1), s + NPIPE - 1);
    }

    const int row0 = bm * GBM + wm * 64 + (lane >> 2);
    const int col0 = bn * GBN + wn * 32 + (lane & 3) * 2;
#pragma unroll
    for (int mt = 0; mt < 4; mt++) {
#pragma unroll
        for (int nt = 0; nt < 4; nt++) {
            const int col = col0 + nt * 8;
            float b0 = bias[col], b1 = bias[col + 1];
#pragma unroll
            for (int half = 0; half < 2; half++) {
                const int row = row0 + mt * 16 + half * 8;
                float v0 = acc[mt][nt][half * 2 + 0] + b0;
                float v1 = acc[mt][nt][half * 2 + 1] + b1;
                if (MODE == 1) { v0 = silu_f(v0); v1 = silu_f(v1); }
                else if (MODE == 2) { v0 = softplus_f(v0); v1 = softplus_f(v1); }
                float2 w; w.x = v0; w.y = v1;
                *(float2*)(C + (size_t)row * DD + col) = w;
            }
        }
    }
}

// ---------------- elementwise split: fp32 -> bf16 hi/lo ----------------
__global__ __launch_bounds__(256)
void split_kernel(const float* __restrict__ X, Bb16* __restrict__ H,
                  Bb16* __restrict__ L, int n4)
{
    for (int i = blockIdx.x * blockDim.x + threadIdx.x; i < n4; i += gridDim.x * blockDim.x) {
        float4 v = ((const float4*)X)[i];
        Bb16 h0, l0, h1, l1, h2, l2, h3, l3;
        split2(v.x, h0, l0); split2(v.y, h1, l1); split2(v.z, h2, l2); split2(v.w, h3, l3);
        __nv_bfloat162 hh0; hh0.x = h0; hh0.y = h1;
        __nv_bfloat162 hh1; hh1.x = h2; hh1.y = h3;
        __nv_bfloat162 ll0; ll0.x = l0; ll0.y = l1;
        __nv_bfloat162 ll1; ll1.x = l2; ll1.y = l3;
        ((__nv_bfloat162*)H)[i * 2]     = hh0;
        ((__nv_bfloat162*)H)[i * 2 + 1] = hh1;
        ((__nv_bfloat162*)L)[i * 2]     = ll0;
        ((__nv_bfloat162*)L)[i * 2 + 1] = ll1;
    }
}

// ---------------- fused transpose+split of all 4 weights (grid.z selects W) ----------------
__global__ __launch_bounds__(256)
void tsplit4_kernel(const float* __restrict__ W0, const float* __restrict__ W1,
                    const float* __restrict__ W2, const float* __restrict__ W3,
                    Bb16* __restrict__ T0h, Bb16* __restrict__ T0l,
                    Bb16* __restrict__ T1h, Bb16* __restrict__ T1l,
                    Bb16* __restrict__ T2h, Bb16* __restrict__ T2l,
                    Bb16* __restrict__ T3h, Bb16* __restrict__ T3l)
{
    __shared__ float s[32][33];
    const int wi = blockIdx.z;
    const float* W = (wi == 0) ? W0 : (wi == 1) ? W1 : (wi == 2) ? W2 : W3;
    Bb16* Th = (wi == 0) ? T0h : (wi == 1) ? T1h : (wi == 2) ? T2h : T3h;
    Bb16* Tl = (wi == 0) ? T0l : (wi == 1) ? T1l : (wi == 2) ? T2l : T3l;
    const int bx = blockIdx.x * 32, by = blockIdx.y * 32;
    const int tx = threadIdx.x, ty = threadIdx.y;  // block (32,8)
#pragma unroll
    for (int j = ty; j < 32; j += 8)
        s[j][tx] = W[(size_t)(by + j) * DD + bx + tx];
    __syncthreads();
#pragma unroll
    for (int j = ty; j < 32; j += 8) {
        float v = s[tx][j];
        Bb16 h, l;
        split2(v, h, l);
        Th[(size_t)(bx + j) * DD + by + tx] = h;
        Tl[(size_t)(bx + j) * DD + by + tx] = l;
    }
}

// ---------------- depthwise conv3 + silu (+ bf16 split out) ----------------
__global__ __launch_bounds__(256)
void conv_silu_kernel(const float* __restrict__ x1, const float* __restrict__ w,
                      const float* __restrict__ cb, float* __restrict__ x3,
                      Bb16* __restrict__ x3h, Bb16* __restrict__ x3l)
{
    const int total2 = BB * TT * DD / 2;
    for (int i2 = blockIdx.x * blockDim.x + threadIdx.x; i2 < total2; i2 += gridDim.x * blockDim.x) {
        int idx = i2 * 2;
        int d = idx & (DD - 1);
        int t = (idx / DD) & (TT - 1);
        float2 xc = *(const float2*)(x1 + idx);
        float c0 = xc.x * w[d * 3 + 1] + cb[d];
        float c1 = xc.y * w[(d + 1) * 3 + 1] + cb[d + 1];
        if (t > 0) {
            float2 xm = *(const float2*)(x1 + idx - DD);
            c0 = fmaf(xm.x, w[d * 3], c0);
            c1 = fmaf(xm.y, w[(d + 1) * 3], c1);
        }
        if (t < TT - 1) {
            float2 xp = *(const float2*)(x1 + idx + DD);
            c0 = fmaf(xp.x, w[d * 3 + 2], c0);
            c1 = fmaf(xp.y, w[(d + 1) * 3 + 2], c1);
        }
        float2 r; r.x = silu_f(c0); r.y = silu_f(c1);
        *(float2*)(x3 + idx) = r;
        Bb16 h0, l0, h1, l1;
        split2(r.x, h0, l0); split2(r.y, h1, l1);
        __nv_bfloat162 hh; hh.x = h0; hh.y = h1;
        __nv_bfloat162 ll; ll.x = l0; ll.y = l1;
        *(__nv_bfloat162*)(x3h + idx) = hh;
        *(__nv_bfloat162*)(x3l + idx) = ll;
    }
}

// ---------------- B/C projections ----------------
__global__ __launch_bounds__(256)
void proj_bc_kernel(const float* __restrict__ X,
                    const float* __restrict__ Wb, const float* __restrict__ Wc,
                    const float* __restrict__ bb, const float* __restrict__ bc,
                    float* __restrict__ Bm, float* __restrict__ Cm)
{
    __shared__ float Xs[32][33];
    __shared__ float Ws[32][32];
    const int tid = threadIdx.x;
    const int row0 = blockIdx.x * 32;
    const int c = tid & 31;
    const int rq = tid >> 5;
    float acc[4] = {0.f, 0.f, 0.f, 0.f};
    const int lr = tid / 8;
    const int lc = (tid % 8) * 4;

    for (int k0 = 0; k0 < DD; k0 += 32) {
        float4 xv = *(const float4*)(X + (size_t)(row0 + lr) * DD + k0 + lc);
        Xs[lr][lc + 0] = xv.x; Xs[lr][lc + 1] = xv.y;
        Xs[lr][lc + 2] = xv.z; Xs[lr][lc + 3] = xv.w;
#pragma unroll
        for (int q = 0; q < 4; q++) {
            int cc = lc + q;
            float wv = (cc < 16) ? Wb[(size_t)(k0 + lr) * 16 + cc]
                                 : Wc[(size_t)(k0 + lr) * 16 + cc - 16];
            Ws[lr][cc] = wv;
        }
        __syncthreads();
#pragma unroll
        for (int kk = 0; kk < 32; kk++) {
            float w = Ws[kk][c];
#pragma unroll
            for (int r = 0; r < 4; r++)
                acc[r] = fmaf(Xs[rq * 4 + r][kk], w, acc[r]);
        }
        __syncthreads();
    }
#pragma unroll
    for (int r = 0; r < 4; r++) {
        int row = row0 + rq * 4 + r;
        if (c < 16) Bm[(size_t)row * 16 + c]      = acc[r] + bb[c];
        else        Cm[(size_t)row * 16 + c - 16] = acc[r] + bc[c - 16];
    }
}

// ---------------- selective scan (outputs bf16 hi/lo of y*z) ----------------
#define SCHUNK 32
__global__ __launch_bounds__(128)
void scan_kernel(const float* __restrict__ dt, const float* __restrict__ x,
                 const float* __restrict__ Bm, const float* __restrict__ Cm,
                 const float* __restrict__ A,  const float* __restrict__ z,
                 Bb16* __restrict__ yh, Bb16* __restrict__ yl)
{
    const int blk = blockIdx.x;
    const int b = blk >> 7;
    const int d0 = (blk & 127) * 8;
    const int tid = threadIdx.x;
    const int n = tid & 15;
    const int dl = tid >> 4;
    const int d = d0 + dl;

    const float a = A[(size_t)d * NN + n];
    float h = 0.f;

    __shared__ float s_dt[SCHUNK][8], s_x[SCHUNK][8], s_z[SCHUNK][8];
    __shared__ float s_B[SCHUNK][16], s_C[SCHUNK][16];
    __shared__ float s_y[SCHUNK][8];

    const size_t base = (size_t)b * TT * DD;
    const int li = tid / 4;
    const int lj2 = (tid % 4) * 2;
    const int lj4 = (tid % 4) * 4;

    for (int t0 = 0; t0 < TT; t0 += SCHUNK) {
        size_t rbase = base + (size_t)(t0 + li) * DD + d0;
        *(float2*)&s_dt[li][lj2] = *(const float2*)(dt + rbase + lj2);
        *(float2*)&s_x [li][lj2] = *(const float2*)(x  + rbase + lj2);
        *(float2*)&s_z [li][lj2] = *(const float2*)(z  + rbase + lj2);
        size_t nbase = ((size_t)b * TT + t0 + li) * NN;
        *(float4*)&s_B[li][lj4] = *(const float4*)(Bm + nbase + lj4);
        *(float4*)&s_C[li][lj4] = *(const float4*)(Cm + nbase + lj4);
        __syncthreads();

#pragma unroll 8
        for (int i = 0; i < SCHUNK; i++) {
            float dtv = s_dt[i][dl];
            float xv  = s_x[i][dl];
            float Bv  = s_B[i][n];
            float Cv  = s_C[i][n];
            float da  = __expf(dtv * a);
            h = fmaf(da, h, dtv * Bv * xv);
            float p = h * Cv;
            p += __shfl_xor_sync(0xffffffffu, p, 1);
            p += __shfl_xor_sync(0xffffffffu, p, 2);
            p += __shfl_xor_sync(0xffffffffu, p, 4);
            p += __shfl_xor_sync(0xffffffffu, p, 8);
            if (n == 0) s_y[i][dl] = p * s_z[i][dl];
        }
        __syncthreads();

        float2 v = *(float2*)&s_y[li][lj2];
        Bb16 h0, l0, h1, l1;
        split2(v.x, h0, l0); split2(v.y, h1, l1);
        __nv_bfloat162 hh; hh.x = h0; hh.y = h1;
        __nv_bfloat162 ll; ll.x = l0; ll.y = l1;
        *(__nv_bfloat162*)(yh + rbase + lj2) = hh;
        *(__nv_bfloat162*)(yl + rbase + lj2) = ll;
        __syncthreads();
    }
}

// ---------------- launch ----------------
extern "C" void kernel_launch(void* const* d_in, const int* in_sizes, int n_in,
                              void* d_out, int out_size)
{
    const float* u    = (const float*)d_in[0];
    const float* Win  = (const float*)d_in[1];
    const float* b_in = (const float*)d_in[2];
    const float* Wg   = (const float*)d_in[3];
    const float* bg   = (const float*)d_in[4];
    const float* Wout = (const float*)d_in[5];
    const float* bout = (const float*)d_in[6];
    const float* convw= (const float*)d_in[7];
    const float* convb= (const float*)d_in[8];
    const float* A    = (const float*)d_in[9];
    const float* Wb   = (const float*)d_in[10];
    const float* bb   = (const float*)d_in[11];
    const float* Wc   = (const float*)d_in[12];
    const float* bc   = (const float*)d_in[13];
    const float* Wdt  = (const float*)d_in[14];
    const float* bdt  = (const float*)d_in[15];
    float* out = (float*)d_out;

    float *x1, *zb, *x3, *dtb, *Bmb, *Cmb;
    cudaGetSymbolAddress((void**)&x1,  g_x1);
    cudaGetSymbolAddress((void**)&zb,  g_z);
    cudaGetSymbolAddress((void**)&x3,  g_x3);
    cudaGetSymbolAddress((void**)&dtb, g_dt);
    cudaGetSymbolAddress((void**)&Bmb, g_Bm);
    cudaGetSymbolAddress((void**)&Cmb, g_Cm);

    Bb16 *uh, *ul, *x3h, *x3l, *yh, *yl;
    Bb16 *Wint_h, *Wint_l, *Wgt_h, *Wgt_l, *Wdtt_h, *Wdtt_l, *Wot_h, *Wot_l;
    cudaGetSymbolAddress((void**)&uh,  g_uh);   cudaGetSymbolAddress((void**)&ul,  g_ul);
    cudaGetSymbolAddress((void**)&x3h, g_x3h);  cudaGetSymbolAddress((void**)&x3l, g_x3l);
    cudaGetSymbolAddress((void**)&yh,  g_yh);   cudaGetSymbolAddress((void**)&yl,  g_yl);
    cudaGetSymbolAddress((void**)&Wint_h, g_Wint_h); cudaGetSymbolAddress((void**)&Wint_l, g_Wint_l);
    cudaGetSymbolAddress((void**)&Wgt_h,  g_Wgt_h);  cudaGetSymbolAddress((void**)&Wgt_l,  g_Wgt_l);
    cudaGetSymbolAddress((void**)&Wdtt_h, g_Wdtt_h); cudaGetSymbolAddress((void**)&Wdtt_l, g_Wdtt_l);
    cudaGetSymbolAddress((void**)&Wot_h,  g_Wot_h);  cudaGetSymbolAddress((void**)&Wot_l,  g_Wot_l);

    cudaFuncSetAttribute((const void*)gemm_mma<0>, cudaFuncAttributeMaxDynamicSharedMemorySize, GEMM_SMEM);
    cudaFuncSetAttribute((const void*)gemm_mma<1>, cudaFuncAttributeMaxDynamicSharedMemorySize, GEMM_SMEM);
    cudaFuncSetAttribute((const void*)gemm_mma<2>, cudaFuncAttributeMaxDynamicSharedMemorySize, GEMM_SMEM);

    // launch #1: fused weight transpose+split (all four weights)
    tsplit4_kernel<<<dim3(32, 32, 4), dim3(32, 8)>>>(Win, Wg, Wdt, Wout,
        Wint_h, Wint_l, Wgt_h, Wgt_l, Wdtt_h, Wdtt_l, Wot_h, Wot_l);
    // launch #2: u split
    split_kernel<<<2048, 256>>>(u, uh, ul, MM * DD / 4);

    dim3 gg(DD / GBN, MM / GBM);  // (8, 32)
    // launch #3: in_proj
    gemm_mma<0><<<gg, 256, GEMM_SMEM>>>(uh, ul, Wint_h, Wint_l, b_in, x1);
    // launch #4 (profiled): gate
    gemm_mma<1><<<gg, 256, GEMM_SMEM>>>(uh, ul, Wgt_h,  Wgt_l,  bg,   zb);
    conv_silu_kernel<<<2048, 256>>>(x1, convw, convb, x3, x3h, x3l);
    gemm_mma<2><<<gg, 256, GEMM_SMEM>>>(x3h, x3l, Wdtt_h, Wdtt_l, bdt, dtb);
    proj_bc_kernel<<<MM / 32, 256>>>(x3, Wb, Wc, bb, bc, Bmb, Cmb);
    scan_kernel<<<BB * (DD / 8), 128>>>(dtb, x3, Bmb, Cmb, A, zb, yh, yl);
    gemm_mma<0><<<gg, 256, GEMM_SMEM>>>(yh, yl, Wot_h, Wot_l, bout, out);
}

// round 7
// speedup vs baseline: 2.0833x; 1.0595x over previous
#include <cuda_runtime.h>
#include <cuda_bf16.h>
#include <math.h>
#include <stdint.h>

#define BB 4
#define TT 1024
#define DD 1024
#define NN 16
#define MM (BB*TT)   // 4096

// GEMM tiling: 128x128 CTA tile, GBK=32, swizzled 64B rows (no padding)
#define Bb16 __nv_bfloat16
#define GBM 128
#define GBN 128
#define GBK 32
#define ROWB 64
#define TILE_B (128*ROWB)       // 8192
#define OFF_AH 0
#define OFF_AL (TILE_B)
#define OFF_BH (2*TILE_B)
#define OFF_BL (3*TILE_B)
#define STAGE_B (4*TILE_B)      // 32768
#define NPIPE 3
#define GEMM_SMEM (NPIPE*STAGE_B)   // 98304
#define NSTAGE (DD/GBK)         // 32

// ---------------- scratch ----------------
__device__ __align__(256) float g_x1[MM*DD];
__device__ __align__(256) float g_z [MM*DD];
__device__ __align__(256) float g_x3[MM*DD];
__device__ __align__(256) float g_dt[MM*DD];
__device__ __align__(256) float g_Bm[MM*NN];
__device__ __align__(256) float g_Cm[MM*NN];

__device__ __align__(256) Bb16 g_uh[MM*DD],  g_ul[MM*DD];
__device__ __align__(256) Bb16 g_x3h[MM*DD], g_x3l[MM*DD];
__device__ __align__(256) Bb16 g_yh[MM*DD],  g_yl[MM*DD];
__device__ __align__(256) Bb16 g_Wint_h[DD*DD], g_Wint_l[DD*DD];
__device__ __align__(256) Bb16 g_Wgt_h [DD*DD], g_Wgt_l [DD*DD];
__device__ __align__(256) Bb16 g_Wdtt_h[DD*DD], g_Wdtt_l[DD*DD];
__device__ __align__(256) Bb16 g_Wot_h [DD*DD], g_Wot_l [DD*DD];

__device__ __forceinline__ float silu_f(float v) { return v / (1.f + __expf(-v)); }
__device__ __forceinline__ float softplus_f(float v) { return (v > 20.f) ? v : log1pf(__expf(v)); }

__device__ __forceinline__ uint32_t smem_to_u32(const void* p) {
    uint32_t a;
    asm("{ .reg .u64 t; cvta.to.shared.u64 t, %1; cvt.u32.u64 %0, t; }" : "=r"(a) : "l"(p));
    return a;
}
__device__ __forceinline__ void cpa16(uint32_t s, const void* g) {
    asm volatile("cp.async.cg.shared.global [%0], [%1], 16;\n" :: "r"(s), "l"(g));
}
__device__ __forceinline__ void cp_commit() { asm volatile("cp.async.commit_group;\n" ::: "memory"); }
template<int N> __device__ __forceinline__ void cp_wait() { asm volatile("cp.async.wait_group %0;\n" :: "n"(N) : "memory"); }

__device__ __forceinline__ void ldsm_x4(uint32_t* r, uint32_t addr) {
    asm volatile("ldmatrix.sync.aligned.m8n8.x4.shared.b16 {%0,%1,%2,%3}, [%4];"
        : "=r"(r[0]), "=r"(r[1]), "=r"(r[2]), "=r"(r[3]) : "r"(addr));
}
__device__ __forceinline__ void ldsm_x2(uint32_t* r, uint32_t addr) {
    asm volatile("ldmatrix.sync.aligned.m8n8.x2.shared.b16 {%0,%1}, [%2];"
        : "=r"(r[0]), "=r"(r[1]) : "r"(addr));
}
__device__ __forceinline__ void mma16816(float* c, const uint32_t* a, const uint32_t* b) {
    asm volatile("mma.sync.aligned.m16n8k16.row.col.f32.bf16.bf16.f32 "
        "{%0,%1,%2,%3}, {%4,%5,%6,%7}, {%8,%9}, {%0,%1,%2,%3};"
        : "+f"(c[0]), "+f"(c[1]), "+f"(c[2]), "+f"(c[3])
        : "r"(a[0]), "r"(a[1]), "r"(a[2]), "r"(a[3]), "r"(b[0]), "r"(b[1]));
}

__device__ __forceinline__ void split2(float v, Bb16& h, Bb16& l) {
    h = __float2bfloat16(v);
    l = __float2bfloat16(v - __bfloat162float(h));
}

// ---------------- 3x-bf16 GEMM, GBK=32, swizzled smem, 3-stage pipeline ----------------
template<int MODE>
__global__ __launch_bounds__(256, 2)
void gemm_mma(const Bb16* __restrict__ Ah, const Bb16* __restrict__ Al,
              const Bb16* __restrict__ Bh, const Bb16* __restrict__ Bl,
              const float* __restrict__ bias, float* __restrict__ C)
{
    extern __shared__ char smem[];
    const uint32_t sb = smem_to_u32(smem);
    const int tid = threadIdx.x;
    const int lane = tid & 31;
    const int wid = tid >> 5;
    const int wm = wid & 1;          // 2 warps in M
    const int wn = wid >> 1;         // 4 warps in N
    const int bn = blockIdx.x, bm = blockIdx.y;

    float acc[4][4][4];
#pragma unroll
    for (int i = 0; i < 4; i++)
#pragma unroll
        for (int j = 0; j < 4; j++)
#pragma unroll
            for (int k = 0; k < 4; k++) acc[i][j][k] = 0.f;

    // loader: row = tid>>1 (0..127); chunk pair = (tid&1)*2 + {0,1}; swizzle c^=((row>>1)&3)
    const int lrow = tid >> 1;
    const int lcp  = (tid & 1) * 2;
    const int lsw  = (lrow >> 1) & 3;
    const uint32_t s_r = (uint32_t)lrow * ROWB;
    const uint32_t sc0 = s_r + (uint32_t)((lcp + 0) ^ lsw) * 16;
    const uint32_t sc1 = s_r + (uint32_t)((lcp + 1) ^ lsw) * 16;

    const Bb16* gAh = Ah + (size_t)(bm * GBM + lrow) * DD + lcp * 8;
    const Bb16* gAl = Al + (size_t)(bm * GBM + lrow) * DD + lcp * 8;
    const Bb16* gBh = Bh + (size_t)(bn * GBN + lrow) * DD + lcp * 8;
    const Bb16* gBl = Bl + (size_t)(bn * GBN + lrow) * DD + lcp * 8;

    auto load_stage = [&](int buf, int s) {
        const uint32_t st = sb + (uint32_t)buf * STAGE_B;
        const size_t k0 = (size_t)s * GBK;
        cpa16(st + OFF_AH + sc0, gAh + k0);
        cpa16(st + OFF_AH + sc1, gAh + k0 + 8);
        cpa16(st + OFF_AL + sc0, gAl + k0);
        cpa16(st + OFF_AL + sc1, gAl + k0 + 8);
        cpa16(st + OFF_BH + sc0, gBh + k0);
        cpa16(st + OFF_BH + sc1, gBh + k0 + 8);
        cpa16(st + OFF_BL + sc0, gBl + k0);
        cpa16(st + OFF_BL + sc1, gBl + k0 + 8);
        cp_commit();
    };

    load_stage(0, 0);
    load_stage(1, 1);

    // ldsm per-lane constants (swizzle folded in; invariant across mt/nt)
    const int rA = lane & 15, hiA = lane >> 4;
    const int swA = (rA >> 1) & 3;
    const uint32_t a_base = OFF_AH + (uint32_t)(wm * 64 + rA) * ROWB;
    const uint32_t acs0 = (uint32_t)((0 + hiA) ^ swA) * 16;
    const uint32_t acs1 = (uint32_t)((2 + hiA) ^ swA) * 16;

    const int rB = lane & 7, hiB = (lane >> 3) & 1;
    const int swB = (rB >> 1) & 3;
    const uint32_t b_base = OFF_BH + (uint32_t)(wn * 32 + rB) * ROWB;
    const uint32_t bcs0 = (uint32_t)((0 + hiB) ^ swB) * 16;
    const uint32_t bcs1 = (uint32_t)((2 + hiB) ^ swB) * 16;

    for (int s = 0; s < NSTAGE; s++) {
        const int buf = s - (s / NPIPE) * NPIPE;
        if (s < NSTAGE - 1) cp_wait<1>(); else cp_wait<0>();
        __syncthreads();

        const uint32_t st = sb + (uint32_t)buf * STAGE_B;
#pragma unroll
        for (int kc = 0; kc < 2; kc++) {
            const uint32_t ac = kc ? acs1 : acs0;
            const uint32_t bc = kc ? bcs1 : bcs0;
            uint32_t bhf[4][2], blf[4][2];
#pragma unroll
            for (int nt = 0; nt < 4; nt++) {
                uint32_t ad = st + b_base + (uint32_t)nt * (8 * ROWB) + bc;
                ldsm_x2(bhf[nt], ad);
                ldsm_x2(blf[nt], ad + TILE_B);
            }
#pragma unroll
            for (int mt = 0; mt < 4; mt++) {
                uint32_t ad = st + a_base + (uint32_t)mt * (16 * ROWB) + ac;
                uint32_t ahf[4], alf[4];
                ldsm_x4(ahf, ad);
                ldsm_x4(alf, ad + TILE_B);
#pragma unroll
                for (int nt = 0; nt < 4; nt++) {
                    mma16816(acc[mt][nt], ahf, bhf[nt]);
                    mma16816(acc[mt][nt], ahf, blf[nt]);
                    mma16816(acc[mt][nt], alf, bhf[nt]);
                }
            }
        }

        if (s + 2 < NSTAGE) {
            int nb = s + 2;
            load_stage(nb - (nb / NPIPE) * NPIPE, nb);
        }
    }

    const int row0 = bm * GBM + wm * 64 + (lane >> 2);
    const int col0 = bn * GBN + wn * 32 + (lane & 3) * 2;
#pragma unroll
    for (int mt = 0; mt < 4; mt++) {
#pragma unroll
        for (int nt = 0; nt < 4; nt++) {
            const int col = col0 + nt * 8;
            float b0 = bias[col], b1 = bias[col + 1];
#pragma unroll
            for (int half = 0; half < 2; half++) {
                const int row = row0 + mt * 16 + half * 8;
                float v0 = acc[mt][nt][half * 2 + 0] + b0;
                float v1 = acc[mt][nt][half * 2 + 1] + b1;
                if (MODE == 1) { v0 = silu_f(v0); v1 = silu_f(v1); }
                else if (MODE == 2) { v0 = softplus_f(v0); v1 = softplus_f(v1); }
                float2 w; w.x = v0; w.y = v1;
                *(float2*)(C + (size_t)row * DD + col) = w;
            }
        }
    }
}

// ---------------- elementwise split: fp32 -> bf16 hi/lo ----------------
__global__ __launch_bounds__(256)
void split_kernel(const float* __restrict__ X, Bb16* __restrict__ H,
                  Bb16* __restrict__ L, int n4)
{
    for (int i = blockIdx.x * blockDim.x + threadIdx.x; i < n4; i += gridDim.x * blockDim.x) {
        float4 v = ((const float4*)X)[i];
        Bb16 h0, l0, h1, l1, h2, l2, h3, l3;
        split2(v.x, h0, l0); split2(v.y, h1, l1); split2(v.z, h2, l2); split2(v.w, h3, l3);
        __nv_bfloat162 hh0; hh0.x = h0; hh0.y = h1;
        __nv_bfloat162 hh1; hh1.x = h2; hh1.y = h3;
        __nv_bfloat162 ll0; ll0.x = l0; ll0.y = l1;
        __nv_bfloat162 ll1; ll1.x = l2; ll1.y = l3;
        ((__nv_bfloat162*)H)[i * 2]     = hh0;
        ((__nv_bfloat162*)H)[i * 2 + 1] = hh1;
        ((__nv_bfloat162*)L)[i * 2]     = ll0;
        ((__nv_bfloat162*)L)[i * 2 + 1] = ll1;
    }
}

// ---------------- fused transpose+split of all 4 weights ----------------
__global__ __launch_bounds__(256)
void tsplit4_kernel(const float* __restrict__ W0, const float* __restrict__ W1,
                    const float* __restrict__ W2, const float* __restrict__ W3,
                    Bb16* __restrict__ T0h, Bb16* __restrict__ T0l,
                    Bb16* __restrict__ T1h, Bb16* __restrict__ T1l,
                    Bb16* __restrict__ T2h, Bb16* __restrict__ T2l,
                    Bb16* __restrict__ T3h, Bb16* __restrict__ T3l)
{
    __shared__ float s[32][33];
    const int wi = blockIdx.z;
    const float* W = (wi == 0) ? W0 : (wi == 1) ? W1 : (wi == 2) ? W2 : W3;
    Bb16* Th = (wi == 0) ? T0h : (wi == 1) ? T1h : (wi == 2) ? T2h : T3h;
    Bb16* Tl = (wi == 0) ? T0l : (wi == 1) ? T1l : (wi == 2) ? T2l : T3l;
    const int bx = blockIdx.x * 32, by = blockIdx.y * 32;
    const int tx = threadIdx.x, ty = threadIdx.y;
#pragma unroll
    for (int j = ty; j < 32; j += 8)
        s[j][tx] = W[(size_t)(by + j) * DD + bx + tx];
    __syncthreads();
#pragma unroll
    for (int j = ty; j < 32; j += 8) {
        float v = s[tx][j];
        Bb16 h, l;
        split2(v, h, l);
        Th[(size_t)(bx + j) * DD + by + tx] = h;
        Tl[(size_t)(bx + j) * DD + by + tx] = l;
    }
}

// ---------------- depthwise conv3 + silu (+ bf16 split out) ----------------
__global__ __launch_bounds__(256)
void conv_silu_kernel(const float* __restrict__ x1, const float* __restrict__ w,
                      const float* __restrict__ cb, float* __restrict__ x3,
                      Bb16* __restrict__ x3h, Bb16* __restrict__ x3l)
{
    const int total2 = BB * TT * DD / 2;
    for (int i2 = blockIdx.x * blockDim.x + threadIdx.x; i2 < total2; i2 += gridDim.x * blockDim.x) {
        int idx = i2 * 2;
        int d = idx & (DD - 1);
        int t = (idx / DD) & (TT - 1);
        float2 xc = *(const float2*)(x1 + idx);
        float c0 = xc.x * w[d * 3 + 1] + cb[d];
        float c1 = xc.y * w[(d + 1) * 3 + 1] + cb[d + 1];
        if (t > 0) {
            float2 xm = *(const float2*)(x1 + idx - DD);
            c0 = fmaf(xm.x, w[d * 3], c0);
            c1 = fmaf(xm.y, w[(d + 1) * 3], c1);
        }
        if (t < TT - 1) {
            float2 xp = *(const float2*)(x1 + idx + DD);
            c0 = fmaf(xp.x, w[d * 3 + 2], c0);
            c1 = fmaf(xp.y, w[(d + 1) * 3 + 2], c1);
        }
        float2 r; r.x = silu_f(c0); r.y = silu_f(c1);
        *(float2*)(x3 + idx) = r;
        Bb16 h0, l0, h1, l1;
        split2(r.x, h0, l0); split2(r.y, h1, l1);
        __nv_bfloat162 hh; hh.x = h0; hh.y = h1;
        __nv_bfloat162 ll; ll.x = l0; ll.y = l1;
        *(__nv_bfloat162*)(x3h + idx) = hh;
        *(__nv_bfloat162*)(x3l + idx) = ll;
    }
}

// ---------------- B/C projections ----------------
__global__ __launch_bounds__(256)
void proj_bc_kernel(const float* __restrict__ X,
                    const float* __restrict__ Wb, const float* __restrict__ Wc,
                    const float* __restrict__ bb, const float* __restrict__ bc,
                    float* __restrict__ Bm, float* __restrict__ Cm)
{
    __shared__ float Xs[32][33];
    __shared__ float Ws[32][32];
    const int tid = threadIdx.x;
    const int row0 = blockIdx.x * 32;
    const int c = tid & 31;
    const int rq = tid >> 5;
    float acc[4] = {0.f, 0.f, 0.f, 0.f};
    const int lr = tid / 8;
    const int lc = (tid % 8) * 4;

    for (int k0 = 0; k0 < DD; k0 += 32) {
        float4 xv = *(const float4*)(X + (size_t)(row0 + lr) * DD + k0 + lc);
        Xs[lr][lc + 0] = xv.x; Xs[lr][lc + 1] = xv.y;
        Xs[lr][lc + 2] = xv.z; Xs[lr][lc + 3] = xv.w;
#pragma unroll
        for (int q = 0; q < 4; q++) {
            int cc = lc + q;
            float wv = (cc < 16) ? Wb[(size_t)(k0 + lr) * 16 + cc]
                                 : Wc[(size_t)(k0 + lr) * 16 + cc - 16];
            Ws[lr][cc] = wv;
        }
        __syncthreads();
#pragma unroll
        for (int kk = 0; kk < 32; kk++) {
            float w = Ws[kk][c];
#pragma unroll
            for (int r = 0; r < 4; r++)
                acc[r] = fmaf(Xs[rq * 4 + r][kk], w, acc[r]);
        }
        __syncthreads();
    }
#pragma unroll
    for (int r = 0; r < 4; r++) {
        int row = row0 + rq * 4 + r;
        if (c < 16) Bm[(size_t)row * 16 + c]      = acc[r] + bb[c];
        else        Cm[(size_t)row * 16 + c - 16] = acc[r] + bc[c - 16];
    }
}

// ---------------- selective scan (outputs bf16 hi/lo of y*z) ----------------
#define SCHUNK 32
__global__ __launch_bounds__(128)
void scan_kernel(const float* __restrict__ dt, const float* __restrict__ x,
                 const float* __restrict__ Bm, const float* __restrict__ Cm,
                 const float* __restrict__ A,  const float* __restrict__ z,
                 Bb16* __restrict__ yh, Bb16* __restrict__ yl)
{
    const int blk = blockIdx.x;
    const int b = blk >> 7;
    const int d0 = (blk & 127) * 8;
    const int tid = threadIdx.x;
    const int n = tid & 15;
    const int dl = tid >> 4;
    const int d = d0 + dl;

    const float a = A[(size_t)d * NN + n];
    float h = 0.f;

    __shared__ float s_dt[SCHUNK][8], s_x[SCHUNK][8], s_z[SCHUNK][8];
    __shared__ float s_B[SCHUNK][16], s_C[SCHUNK][16];
    __shared__ float s_y[SCHUNK][8];

    const size_t base = (size_t)b * TT * DD;
    const int li = tid / 4;
    const int lj2 = (tid % 4) * 2;
    const int lj4 = (tid % 4) * 4;

    for (int t0 = 0; t0 < TT; t0 += SCHUNK) {
        size_t rbase = base + (size_t)(t0 + li) * DD + d0;
        *(float2*)&s_dt[li][lj2] = *(const float2*)(dt + rbase + lj2);
        *(float2*)&s_x [li][lj2] = *(const float2*)(x  + rbase + lj2);
        *(float2*)&s_z [li][lj2] = *(const float2*)(z  + rbase + lj2);
        size_t nbase = ((size_t)b * TT + t0 + li) * NN;
        *(float4*)&s_B[li][lj4] = *(const float4*)(Bm + nbase + lj4);
        *(float4*)&s_C[li][lj4] = *(const float4*)(Cm + nbase + lj4);
        __syncthreads();

#pragma unroll 8
        for (int i = 0; i < SCHUNK; i++) {
            float dtv = s_dt[i][dl];
            float xv  = s_x[i][dl];
            float Bv  = s_B[i][n];
            float Cv  = s_C[i][n];
            float da  = __expf(dtv * a);
            h = fmaf(da, h, dtv * Bv * xv);
            float p = h * Cv;
            p += __shfl_xor_sync(0xffffffffu, p, 1);
            p += __shfl_xor_sync(0xffffffffu, p, 2);
            p += __shfl_xor_sync(0xffffffffu, p, 4);
            p += __shfl_xor_sync(0xffffffffu, p, 8);
            if (n == 0) s_y[i][dl] = p * s_z[i][dl];
        }
        __syncthreads();

        float2 v = *(float2*)&s_y[li][lj2];
        Bb16 h0, l0, h1, l1;
        split2(v.x, h0, l0); split2(v.y, h1, l1);
        __nv_bfloat162 hh; hh.x = h0; hh.y = h1;
        __nv_bfloat162 ll; ll.x = l0; ll.y = l1;
        *(__nv_bfloat162*)(yh + rbase + lj2) = hh;
        *(__nv_bfloat162*)(yl + rbase + lj2) = ll;
        __syncthreads();
    }
}

// ---------------- launch (fork-join onto a second captured stream) ----------------
extern "C" void kernel_launch(void* const* d_in, const int* in_sizes, int n_in,
                              void* d_out, int out_size)
{
    const float* u    = (const float*)d_in[0];
    const float* Win  = (const float*)d_in[1];
    const float* b_in = (const float*)d_in[2];
    const float* Wg   = (const float*)d_in[3];
    const float* bg   = (const float*)d_in[4];
    const float* Wout = (const float*)d_in[5];
    const float* bout = (const float*)d_in[6];
    const float* convw= (const float*)d_in[7];
    const float* convb= (const float*)d_in[8];
    const float* A    = (const float*)d_in[9];
    const float* Wb   = (const float*)d_in[10];
    const float* bb   = (const float*)d_in[11];
    const float* Wc   = (const float*)d_in[12];
    const float* bc   = (const float*)d_in[13];
    const float* Wdt  = (const float*)d_in[14];
    const float* bdt  = (const float*)d_in[15];
    float* out = (float*)d_out;

    float *x1, *zb, *x3, *dtb, *Bmb, *Cmb;
    cudaGetSymbolAddress((void**)&x1,  g_x1);
    cudaGetSymbolAddress((void**)&zb,  g_z);
    cudaGetSymbolAddress((void**)&x3,  g_x3);
    cudaGetSymbolAddress((void**)&dtb, g_dt);
    cudaGetSymbolAddress((void**)&Bmb, g_Bm);
    cudaGetSymbolAddress((void**)&Cmb, g_Cm);

    Bb16 *uh, *ul, *x3h, *x3l, *yh, *yl;
    Bb16 *Wint_h, *Wint_l, *Wgt_h, *Wgt_l, *Wdtt_h, *Wdtt_l, *Wot_h, *Wot_l;
    cudaGetSymbolAddress((void**)&uh,  g_uh);   cudaGetSymbolAddress((void**)&ul,  g_ul);
    cudaGetSymbolAddress((void**)&x3h, g_x3h);  cudaGetSymbolAddress((void**)&x3l, g_x3l);
    cudaGetSymbolAddress((void**)&yh,  g_yh);   cudaGetSymbolAddress((void**)&yl,  g_yl);
    cudaGetSymbolAddress((void**)&Wint_h, g_Wint_h); cudaGetSymbolAddress((void**)&Wint_l, g_Wint_l);
    cudaGetSymbolAddress((void**)&Wgt_h,  g_Wgt_h);  cudaGetSymbolAddress((void**)&Wgt_l,  g_Wgt_l);
    cudaGetSymbolAddress((void**)&Wdtt_h, g_Wdtt_h); cudaGetSymbolAddress((void**)&Wdtt_l, g_Wdtt_l);
    cudaGetSymbolAddress((void**)&Wot_h,  g_Wot_h);  cudaGetSymbolAddress((void**)&Wot_l,  g_Wot_l);

    cudaFuncSetAttribute((const void*)gemm_mma<0>, cudaFuncAttributeMaxDynamicSharedMemorySize, GEMM_SMEM);
    cudaFuncSetAttribute((const void*)gemm_mma<1>, cudaFuncAttributeMaxDynamicSharedMemorySize, GEMM_SMEM);
    cudaFuncSetAttribute((const void*)gemm_mma<2>, cudaFuncAttributeMaxDynamicSharedMemorySize, GEMM_SMEM);

    // side stream + events (host-side objects, created once; no device memory)
    static cudaStream_t s1 = nullptr;
    static cudaEvent_t evA = nullptr, evG = nullptr, evC = nullptr, evP = nullptr;
    if (!s1) {
        cudaStreamCreateWithFlags(&s1, cudaStreamNonBlocking);
        cudaEventCreateWithFlags(&evA, cudaEventDisableTiming);
        cudaEventCreateWithFlags(&evG, cudaEventDisableTiming);
        cudaEventCreateWithFlags(&evC, cudaEventDisableTiming);
        cudaEventCreateWithFlags(&evP, cudaEventDisableTiming);
    }
    cudaStream_t s0 = 0;

    dim3 gg(DD / GBN, MM / GBM);  // (8, 32)

    tsplit4_kernel<<<dim3(32, 32, 4), dim3(32, 8), 0, s0>>>(Win, Wg, Wdt, Wout,
        Wint_h, Wint_l, Wgt_h, Wgt_l, Wdtt_h, Wdtt_l, Wot_h, Wot_l);
    split_kernel<<<2048, 256, 0, s0>>>(u, uh, ul, MM * DD / 4);
    cudaEventRecord(evA, s0);

    // fork: gate GEMM on s1 (independent of x1 chain)
    cudaStreamWaitEvent(s1, evA, 0);
    gemm_mma<1><<<gg, 256, GEMM_SMEM, s1>>>(uh, ul, Wgt_h, Wgt_l, bg, zb);
    cudaEventRecord(evG, s1);

    // main chain on s0
    gemm_mma<0><<<gg, 256, GEMM_SMEM, s0>>>(uh, ul, Wint_h, Wint_l, b_in, x1);
    conv_silu_kernel<<<2048, 256, 0, s0>>>(x1, convw, convb, x3, x3h, x3l);
    cudaEventRecord(evC, s0);

    // fork: B/C projections on s1 (needs x3 only)
    cudaStreamWaitEvent(s1, evC, 0);
    proj_bc_kernel<<<MM / 32, 256, 0, s1>>>(x3, Wb, Wc, bb, bc, Bmb, Cmb);
    cudaEventRecord(evP, s1);

    gemm_mma<2><<<gg, 256, GEMM_SMEM, s0>>>(x3h, x3l, Wdtt_h, Wdtt_l, bdt, dtb);

    // join: scan needs dt (s0), Bm/Cm (s1), z (s1)
    cudaStreamWaitEvent(s0, evG, 0);
    cudaStreamWaitEvent(s0, evP, 0);
    scan_kernel<<<BB * (DD / 8), 128, 0, s0>>>(dtb, x3, Bmb, Cmb, A, zb, yh, yl);
    gemm_mma<0><<<gg, 256, GEMM_SMEM, s0>>>(yh, yl, Wot_h, Wot_l, bout, out);
}

// round 8
// speedup vs baseline: 2.1066x; 1.0112x over previous
#include <cuda_runtime.h>
#include <cuda_bf16.h>
#include <math.h>
#include <stdint.h>

#define BB 4
#define TT 1024
#define DD 1024
#define NN 16
#define MM (BB*TT)   // 4096

// GEMM tiling: 128x128 CTA tile, GBK=32, swizzled 64B rows (no padding)
#define Bb16 __nv_bfloat16
#define GBM 128
#define GBN 128
#define GBK 32
#define ROWB 64
#define TILE_B (128*ROWB)       // 8192
#define OFF_AH 0
#define OFF_AL (TILE_B)
#define OFF_BH (2*TILE_B)
#define OFF_BL (3*TILE_B)
#define STAGE_B (4*TILE_B)      // 32768
#define NPIPE 3
#define GEMM_SMEM (NPIPE*STAGE_B)   // 98304
#define NSTAGE (DD/GBK)         // 32

// ---------------- scratch ----------------
__device__ __align__(256) float g_x1[MM*DD];
__device__ __align__(256) float g_z [MM*DD];
__device__ __align__(256) float g_x3[MM*DD];
__device__ __align__(256) float g_dt[MM*DD];
__device__ __align__(256) float g_Bm[MM*NN];
__device__ __align__(256) float g_Cm[MM*NN];

__device__ __align__(256) Bb16 g_uh[MM*DD],  g_ul[MM*DD];
__device__ __align__(256) Bb16 g_x3h[MM*DD], g_x3l[MM*DD];
__device__ __align__(256) Bb16 g_yh[MM*DD],  g_yl[MM*DD];
__device__ __align__(256) Bb16 g_Wint_h[DD*DD], g_Wint_l[DD*DD];
__device__ __align__(256) Bb16 g_Wgt_h [DD*DD], g_Wgt_l [DD*DD];
__device__ __align__(256) Bb16 g_Wdtt_h[DD*DD], g_Wdtt_l[DD*DD];
__device__ __align__(256) Bb16 g_Wot_h [DD*DD], g_Wot_l [DD*DD];

__device__ __forceinline__ float silu_f(float v) { return v / (1.f + __expf(-v)); }
__device__ __forceinline__ float softplus_f(float v) { return (v > 20.f) ? v : log1pf(__expf(v)); }

__device__ __forceinline__ uint32_t smem_to_u32(const void* p) {
    uint32_t a;
    asm("{ .reg .u64 t; cvta.to.shared.u64 t, %1; cvt.u32.u64 %0, t; }" : "=r"(a) : "l"(p));
    return a;
}
__device__ __forceinline__ void cpa16(uint32_t s, const void* g) {
    asm volatile("cp.async.cg.shared.global [%0], [%1], 16;\n" :: "r"(s), "l"(g));
}
__device__ __forceinline__ void cp_commit() { asm volatile("cp.async.commit_group;\n" ::: "memory"); }
template<int N> __device__ __forceinline__ void cp_wait() { asm volatile("cp.async.wait_group %0;\n" :: "n"(N) : "memory"); }

__device__ __forceinline__ void ldsm_x4(uint32_t* r, uint32_t addr) {
    asm volatile("ldmatrix.sync.aligned.m8n8.x4.shared.b16 {%0,%1,%2,%3}, [%4];"
        : "=r"(r[0]), "=r"(r[1]), "=r"(r[2]), "=r"(r[3]) : "r"(addr));
}
__device__ __forceinline__ void ldsm_x2(uint32_t* r, uint32_t addr) {
    asm volatile("ldmatrix.sync.aligned.m8n8.x2.shared.b16 {%0,%1}, [%2];"
        : "=r"(r[0]), "=r"(r[1]) : "r"(addr));
}
__device__ __forceinline__ void mma16816(float* c, const uint32_t* a, const uint32_t* b) {
    asm volatile("mma.sync.aligned.m16n8k16.row.col.f32.bf16.bf16.f32 "
        "{%0,%1,%2,%3}, {%4,%5,%6,%7}, {%8,%9}, {%0,%1,%2,%3};"
        : "+f"(c[0]), "+f"(c[1]), "+f"(c[2]), "+f"(c[3])
        : "r"(a[0]), "r"(a[1]), "r"(a[2]), "r"(a[3]), "r"(b[0]), "r"(b[1]));
}

__device__ __forceinline__ void split2(float v, Bb16& h, Bb16& l) {
    h = __float2bfloat16(v);
    l = __float2bfloat16(v - __bfloat162float(h));
}

// ---------------- 3x-bf16 GEMM, pass-major MMA ordering ----------------
template<int MODE>
__global__ __launch_bounds__(256, 2)
void gemm_mma(const Bb16* __restrict__ Ah, const Bb16* __restrict__ Al,
              const Bb16* __restrict__ Bh, const Bb16* __restrict__ Bl,
              const float* __restrict__ bias, float* __restrict__ C)
{
    extern __shared__ char smem[];
    const uint32_t sb = smem_to_u32(smem);
    const int tid = threadIdx.x;
    const int lane = tid & 31;
    const int wid = tid >> 5;
    const int wm = wid & 1;          // 2 warps in M
    const int wn = wid >> 1;         // 4 warps in N
    const int bn = blockIdx.x, bm = blockIdx.y;

    float acc[4][4][4];
#pragma unroll
    for (int i = 0; i < 4; i++)
#pragma unroll
        for (int j = 0; j < 4; j++)
#pragma unroll
            for (int k = 0; k < 4; k++) acc[i][j][k] = 0.f;

    // loader: row = tid>>1 (0..127); chunk pair = (tid&1)*2 + {0,1}; swizzle c^=((row>>1)&3)
    const int lrow = tid >> 1;
    const int lcp  = (tid & 1) * 2;
    const int lsw  = (lrow >> 1) & 3;
    const uint32_t s_r = (uint32_t)lrow * ROWB;
    const uint32_t sc0 = s_r + (uint32_t)((lcp + 0) ^ lsw) * 16;
    const uint32_t sc1 = s_r + (uint32_t)((lcp + 1) ^ lsw) * 16;

    const Bb16* gAh = Ah + (size_t)(bm * GBM + lrow) * DD + lcp * 8;
    const Bb16* gAl = Al + (size_t)(bm * GBM + lrow) * DD + lcp * 8;
    const Bb16* gBh = Bh + (size_t)(bn * GBN + lrow) * DD + lcp * 8;
    const Bb16* gBl = Bl + (size_t)(bn * GBN + lrow) * DD + lcp * 8;

    auto load_stage = [&](int buf, int s) {
        const uint32_t st = sb + (uint32_t)buf * STAGE_B;
        const size_t k0 = (size_t)s * GBK;
        cpa16(st + OFF_AH + sc0, gAh + k0);
        cpa16(st + OFF_AH + sc1, gAh + k0 + 8);
        cpa16(st + OFF_AL + sc0, gAl + k0);
        cpa16(st + OFF_AL + sc1, gAl + k0 + 8);
        cpa16(st + OFF_BH + sc0, gBh + k0);
        cpa16(st + OFF_BH + sc1, gBh + k0 + 8);
        cpa16(st + OFF_BL + sc0, gBl + k0);
        cpa16(st + OFF_BL + sc1, gBl + k0 + 8);
        cp_commit();
    };

    load_stage(0, 0);
    load_stage(1, 1);

    // ldsm per-lane constants (swizzle folded in)
    const int rA = lane & 15, hiA = lane >> 4;
    const int swA = (rA >> 1) & 3;
    const uint32_t a_base = OFF_AH + (uint32_t)(wm * 64 + rA) * ROWB;
    const uint32_t acs0 = (uint32_t)((0 + hiA) ^ swA) * 16;
    const uint32_t acs1 = (uint32_t)((2 + hiA) ^ swA) * 16;

    const int rB = lane & 7, hiB = (lane >> 3) & 1;
    const int swB = (rB >> 1) & 3;
    const uint32_t b_base = OFF_BH + (uint32_t)(wn * 32 + rB) * ROWB;
    const uint32_t bcs0 = (uint32_t)((0 + hiB) ^ swB) * 16;
    const uint32_t bcs1 = (uint32_t)((2 + hiB) ^ swB) * 16;

    for (int s = 0; s < NSTAGE; s++) {
        const int buf = s - (s / NPIPE) * NPIPE;
        if (s < NSTAGE - 1) cp_wait<1>(); else cp_wait<0>();
        __syncthreads();

        const uint32_t st = sb + (uint32_t)buf * STAGE_B;
#pragma unroll
        for (int kc = 0; kc < 2; kc++) {
            const uint32_t ac = kc ? acs1 : acs0;
            const uint32_t bc = kc ? bcs1 : bcs0;
            uint32_t bhf[4][2], blf[4][2];
#pragma unroll
            for (int nt = 0; nt < 4; nt++) {
                uint32_t ad = st + b_base + (uint32_t)nt * (8 * ROWB) + bc;
                ldsm_x2(bhf[nt], ad);
                ldsm_x2(blf[nt], ad + TILE_B);
            }
            // process M in pairs: pass-major to break accumulator chains
#pragma unroll
            for (int mtp = 0; mtp < 2; mtp++) {
                uint32_t ahf[2][4], alf[2][4];
#pragma unroll
                for (int i = 0; i < 2; i++) {
                    uint32_t ad = st + a_base + (uint32_t)(mtp * 2 + i) * (16 * ROWB) + ac;
                    ldsm_x4(ahf[i], ad);
                    ldsm_x4(alf[i], ad + TILE_B);
                }
                // pass HH: 8 independent accumulators
#pragma unroll
                for (int i = 0; i < 2; i++)
#pragma unroll
                    for (int nt = 0; nt < 4; nt++)
                        mma16816(acc[mtp * 2 + i][nt], ahf[i], bhf[nt]);
                // pass HL
#pragma unroll
                for (int i = 0; i < 2; i++)
#pragma unroll
                    for (int nt = 0; nt < 4; nt++)
                        mma16816(acc[mtp * 2 + i][nt], ahf[i], blf[nt]);
                // pass LH
#pragma unroll
                for (int i = 0; i < 2; i++)
#pragma unroll
                    for (int nt = 0; nt < 4; nt++)
                        mma16816(acc[mtp * 2 + i][nt], alf[i], bhf[nt]);
            }
        }

        if (s + 2 < NSTAGE) {
            int nb = s + 2;
            load_stage(nb - (nb / NPIPE) * NPIPE, nb);
        }
    }

    const int row0 = bm * GBM + wm * 64 + (lane >> 2);
    const int col0 = bn * GBN + wn * 32 + (lane & 3) * 2;
#pragma unroll
    for (int mt = 0; mt < 4; mt++) {
#pragma unroll
        for (int nt = 0; nt < 4; nt++) {
            const int col = col0 + nt * 8;
            float b0 = bias[col], b1 = bias[col + 1];
#pragma unroll
            for (int half = 0; half < 2; half++) {
                const int row = row0 + mt * 16 + half * 8;
                float v0 = acc[mt][nt][half * 2 + 0] + b0;
                float v1 = acc[mt][nt][half * 2 + 1] + b1;
                if (MODE == 1) { v0 = silu_f(v0); v1 = silu_f(v1); }
                else if (MODE == 2) { v0 = softplus_f(v0); v1 = softplus_f(v1); }
                float2 w; w.x = v0; w.y = v1;
                *(float2*)(C + (size_t)row * DD + col) = w;
            }
        }
    }
}

// ---------------- elementwise split: fp32 -> bf16 hi/lo ----------------
__global__ __launch_bounds__(256)
void split_kernel(const float* __restrict__ X, Bb16* __restrict__ H,
                  Bb16* __restrict__ L, int n4)
{
    for (int i = blockIdx.x * blockDim.x + threadIdx.x; i < n4; i += gridDim.x * blockDim.x) {
        float4 v = ((const float4*)X)[i];
        Bb16 h0, l0, h1, l1, h2, l2, h3, l3;
        split2(v.x, h0, l0); split2(v.y, h1, l1); split2(v.z, h2, l2); split2(v.w, h3, l3);
        __nv_bfloat162 hh0; hh0.x = h0; hh0.y = h1;
        __nv_bfloat162 hh1; hh1.x = h2; hh1.y = h3;
        __nv_bfloat162 ll0; ll0.x = l0; ll0.y = l1;
        __nv_bfloat162 ll1; ll1.x = l2; ll1.y = l3;
        ((__nv_bfloat162*)H)[i * 2]     = hh0;
        ((__nv_bfloat162*)H)[i * 2 + 1] = hh1;
        ((__nv_bfloat162*)L)[i * 2]     = ll0;
        ((__nv_bfloat162*)L)[i * 2 + 1] = ll1;
    }
}

// ---------------- fused transpose+split of all 4 weights ----------------
__global__ __launch_bounds__(256)
void tsplit4_kernel(const float* __restrict__ W0, const float* __restrict__ W1,
                    const float* __restrict__ W2, const float* __restrict__ W3,
                    Bb16* __restrict__ T0h, Bb16* __restrict__ T0l,
                    Bb16* __restrict__ T1h, Bb16* __restrict__ T1l,
                    Bb16* __restrict__ T2h, Bb16* __restrict__ T2l,
                    Bb16* __restrict__ T3h, Bb16* __restrict__ T3l)
{
    __shared__ float s[32][33];
    const int wi = blockIdx.z;
    const float* W = (wi == 0) ? W0 : (wi == 1) ? W1 : (wi == 2) ? W2 : W3;
    Bb16* Th = (wi == 0) ? T0h : (wi == 1) ? T1h : (wi == 2) ? T2h : T3h;
    Bb16* Tl = (wi == 0) ? T0l : (wi == 1) ? T1l : (wi == 2) ? T2l : T3l;
    const int bx = blockIdx.x * 32, by = blockIdx.y * 32;
    const int tx = threadIdx.x, ty = threadIdx.y;
#pragma unroll
    for (int j = ty; j < 32; j += 8)
        s[j][tx] = W[(size_t)(by + j) * DD + bx + tx];
    __syncthreads();
#pragma unroll
    for (int j = ty; j < 32; j += 8) {
        float v = s[tx][j];
        Bb16 h, l;
        split2(v, h, l);
        Th[(size_t)(bx + j) * DD + by + tx] = h;
        Tl[(size_t)(bx + j) * DD + by + tx] = l;
    }
}

// ---------------- depthwise conv3 + silu (+ bf16 split out) ----------------
__global__ __launch_bounds__(256)
void conv_silu_kernel(const float* __restrict__ x1, const float* __restrict__ w,
                      const float* __restrict__ cb, float* __restrict__ x3,
                      Bb16* __restrict__ x3h, Bb16* __restrict__ x3l)
{
    const int total2 = BB * TT * DD / 2;
    for (int i2 = blockIdx.x * blockDim.x + threadIdx.x; i2 < total2; i2 += gridDim.x * blockDim.x) {
        int idx = i2 * 2;
        int d = idx & (DD - 1);
        int t = (idx / DD) & (TT - 1);
        float2 xc = *(const float2*)(x1 + idx);
        float c0 = xc.x * w[d * 3 + 1] + cb[d];
        float c1 = xc.y * w[(d + 1) * 3 + 1] + cb[d + 1];
        if (t > 0) {
            float2 xm = *(const float2*)(x1 + idx - DD);
            c0 = fmaf(xm.x, w[d * 3], c0);
            c1 = fmaf(xm.y, w[(d + 1) * 3], c1);
        }
        if (t < TT - 1) {
            float2 xp = *(const float2*)(x1 + idx + DD);
            c0 = fmaf(xp.x, w[d * 3 + 2], c0);
            c1 = fmaf(xp.y, w[(d + 1) * 3 + 2], c1);
        }
        float2 r; r.x = silu_f(c0); r.y = silu_f(c1);
        *(float2*)(x3 + idx) = r;
        Bb16 h0, l0, h1, l1;
        split2(r.x, h0, l0); split2(r.y, h1, l1);
        __nv_bfloat162 hh; hh.x = h0; hh.y = h1;
        __nv_bfloat162 ll; ll.x = l0; ll.y = l1;
        *(__nv_bfloat162*)(x3h + idx) = hh;
        *(__nv_bfloat162*)(x3l + idx) = ll;
    }
}

// ---------------- B/C projections ----------------
__global__ __launch_bounds__(256)
void proj_bc_kernel(const float* __restrict__ X,
                    const float* __restrict__ Wb, const float* __restrict__ Wc,
                    const float* __restrict__ bb, const float* __restrict__ bc,
                    float* __restrict__ Bm, float* __restrict__ Cm)
{
    __shared__ float Xs[32][33];
    __shared__ float Ws[32][32];
    const int tid = threadIdx.x;
    const int row0 = blockIdx.x * 32;
    const int c = tid & 31;
    const int rq = tid >> 5;
    float acc[4] = {0.f, 0.f, 0.f, 0.f};
    const int lr = tid / 8;
    const int lc = (tid % 8) * 4;

    for (int k0 = 0; k0 < DD; k0 += 32) {
        float4 xv = *(const float4*)(X + (size_t)(row0 + lr) * DD + k0 + lc);
        Xs[lr][lc + 0] = xv.x; Xs[lr][lc + 1] = xv.y;
        Xs[lr][lc + 2] = xv.z; Xs[lr][lc + 3] = xv.w;
#pragma unroll
        for (int q = 0; q < 4; q++) {
            int cc = lc + q;
            float wv = (cc < 16) ? Wb[(size_t)(k0 + lr) * 16 + cc]
                                 : Wc[(size_t)(k0 + lr) * 16 + cc - 16];
            Ws[lr][cc] = wv;
        }
        __syncthreads();
#pragma unroll
        for (int kk = 0; kk < 32; kk++) {
            float w = Ws[kk][c];
#pragma unroll
            for (int r = 0; r < 4; r++)
                acc[r] = fmaf(Xs[rq * 4 + r][kk], w, acc[r]);
        }
        __syncthreads();
    }
#pragma unroll
    for (int r = 0; r < 4; r++) {
        int row = row0 + rq * 4 + r;
        if (c < 16) Bm[(size_t)row * 16 + c]      = acc[r] + bb[c];
        else        Cm[(size_t)row * 16 + c - 16] = acc[r] + bc[c - 16];
    }
}

// ---------------- selective scan (outputs bf16 hi/lo of y*z) ----------------
#define SCHUNK 32
__global__ __launch_bounds__(128)
void scan_kernel(const float* __restrict__ dt, const float* __restrict__ x,
                 const float* __restrict__ Bm, const float* __restrict__ Cm,
                 const float* __restrict__ A,  const float* __restrict__ z,
                 Bb16* __restrict__ yh, Bb16* __restrict__ yl)
{
    const int blk = blockIdx.x;
    const int b = blk >> 7;
    const int d0 = (blk & 127) * 8;
    const int tid = threadIdx.x;
    const int n = tid & 15;
    const int dl = tid >> 4;
    const int d = d0 + dl;

    const float a = A[(size_t)d * NN + n];
    float h = 0.f;

    __shared__ float s_dt[SCHUNK][8], s_x[SCHUNK][8], s_z[SCHUNK][8];
    __shared__ float s_B[SCHUNK][16], s_C[SCHUNK][16];
    __shared__ float s_y[SCHUNK][8];

    const size_t base = (size_t)b * TT * DD;
    const int li = tid / 4;
    const int lj2 = (tid % 4) * 2;
    const int lj4 = (tid % 4) * 4;

    for (int t0 = 0; t0 < TT; t0 += SCHUNK) {
        size_t rbase = base + (size_t)(t0 + li) * DD + d0;
        *(float2*)&s_dt[li][lj2] = *(const float2*)(dt + rbase + lj2);
        *(float2*)&s_x [li][lj2] = *(const float2*)(x  + rbase + lj2);
        *(float2*)&s_z [li][lj2] = *(const float2*)(z  + rbase + lj2);
        size_t nbase = ((size_t)b * TT + t0 + li) * NN;
        *(float4*)&s_B[li][lj4] = *(const float4*)(Bm + nbase + lj4);
        *(float4*)&s_C[li][lj4] = *(const float4*)(Cm + nbase + lj4);
        __syncthreads();

#pragma unroll 8
        for (int i = 0; i < SCHUNK; i++) {
            float dtv = s_dt[i][dl];
            float xv  = s_x[i][dl];
            float Bv  = s_B[i][n];
            float Cv  = s_C[i][n];
            float da  = __expf(dtv * a);
            h = fmaf(da, h, dtv * Bv * xv);
            float p = h * Cv;
            p += __shfl_xor_sync(0xffffffffu, p, 1);
            p += __shfl_xor_sync(0xffffffffu, p, 2);
            p += __shfl_xor_sync(0xffffffffu, p, 4);
            p += __shfl_xor_sync(0xffffffffu, p, 8);
            if (n == 0) s_y[i][dl] = p * s_z[i][dl];
        }
        __syncthreads();

        float2 v = *(float2*)&s_y[li][lj2];
        Bb16 h0, l0, h1, l1;
        split2(v.x, h0, l0); split2(v.y, h1, l1);
        __nv_bfloat162 hh; hh.x = h0; hh.y = h1;
        __nv_bfloat162 ll; ll.x = l0; ll.y = l1;
        *(__nv_bfloat162*)(yh + rbase + lj2) = hh;
        *(__nv_bfloat162*)(yl + rbase + lj2) = ll;
        __syncthreads();
    }
}

// ---------------- launch (fork-join onto a second captured stream) ----------------
extern "C" void kernel_launch(void* const* d_in, const int* in_sizes, int n_in,
                              void* d_out, int out_size)
{
    const float* u    = (const float*)d_in[0];
    const float* Win  = (const float*)d_in[1];
    const float* b_in = (const float*)d_in[2];
    const float* Wg   = (const float*)d_in[3];
    const float* bg   = (const float*)d_in[4];
    const float* Wout = (const float*)d_in[5];
    const float* bout = (const float*)d_in[6];
    const float* convw= (const float*)d_in[7];
    const float* convb= (const float*)d_in[8];
    const float* A    = (const float*)d_in[9];
    const float* Wb   = (const float*)d_in[10];
    const float* bb   = (const float*)d_in[11];
    const float* Wc   = (const float*)d_in[12];
    const float* bc   = (const float*)d_in[13];
    const float* Wdt  = (const float*)d_in[14];
    const float* bdt  = (const float*)d_in[15];
    float* out = (float*)d_out;

    float *x1, *zb, *x3, *dtb, *Bmb, *Cmb;
    cudaGetSymbolAddress((void**)&x1,  g_x1);
    cudaGetSymbolAddress((void**)&zb,  g_z);
    cudaGetSymbolAddress((void**)&x3,  g_x3);
    cudaGetSymbolAddress((void**)&dtb, g_dt);
    cudaGetSymbolAddress((void**)&Bmb, g_Bm);
    cudaGetSymbolAddress((void**)&Cmb, g_Cm);

    Bb16 *uh, *ul, *x3h, *x3l, *yh, *yl;
    Bb16 *Wint_h, *Wint_l, *Wgt_h, *Wgt_l, *Wdtt_h, *Wdtt_l, *Wot_h, *Wot_l;
    cudaGetSymbolAddress((void**)&uh,  g_uh);   cudaGetSymbolAddress((void**)&ul,  g_ul);
    cudaGetSymbolAddress((void**)&x3h, g_x3h);  cudaGetSymbolAddress((void**)&x3l, g_x3l);
    cudaGetSymbolAddress((void**)&yh,  g_yh);   cudaGetSymbolAddress((void**)&yl,  g_yl);
    cudaGetSymbolAddress((void**)&Wint_h, g_Wint_h); cudaGetSymbolAddress((void**)&Wint_l, g_Wint_l);
    cudaGetSymbolAddress((void**)&Wgt_h,  g_Wgt_h);  cudaGetSymbolAddress((void**)&Wgt_l,  g_Wgt_l);
    cudaGetSymbolAddress((void**)&Wdtt_h, g_Wdtt_h); cudaGetSymbolAddress((void**)&Wdtt_l, g_Wdtt_l);
    cudaGetSymbolAddress((void**)&Wot_h,  g_Wot_h);  cudaGetSymbolAddress((void**)&Wot_l,  g_Wot_l);

    cudaFuncSetAttribute((const void*)gemm_mma<0>, cudaFuncAttributeMaxDynamicSharedMemorySize, GEMM_SMEM);
    cudaFuncSetAttribute((const void*)gemm_mma<1>, cudaFuncAttributeMaxDynamicSharedMemorySize, GEMM_SMEM);
    cudaFuncSetAttribute((const void*)gemm_mma<2>, cudaFuncAttributeMaxDynamicSharedMemorySize, GEMM_SMEM);

    static cudaStream_t s1 = nullptr;
    static cudaEvent_t evA = nullptr, evG = nullptr, evC = nullptr, evP = nullptr;
    if (!s1) {
        cudaStreamCreateWithFlags(&s1, cudaStreamNonBlocking);
        cudaEventCreateWithFlags(&evA, cudaEventDisableTiming);
        cudaEventCreateWithFlags(&evG, cudaEventDisableTiming);
        cudaEventCreateWithFlags(&evC, cudaEventDisableTiming);
        cudaEventCreateWithFlags(&evP, cudaEventDisableTiming);
    }
    cudaStream_t s0 = 0;

    dim3 gg(DD / GBN, MM / GBM);  // (8, 32)

    tsplit4_kernel<<<dim3(32, 32, 4), dim3(32, 8), 0, s0>>>(Win, Wg, Wdt, Wout,
        Wint_h, Wint_l, Wgt_h, Wgt_l, Wdtt_h, Wdtt_l, Wot_h, Wot_l);
    split_kernel<<<2048, 256, 0, s0>>>(u, uh, ul, MM * DD / 4);
    cudaEventRecord(evA, s0);

    cudaStreamWaitEvent(s1, evA, 0);
    gemm_mma<1><<<gg, 256, GEMM_SMEM, s1>>>(uh, ul, Wgt_h, Wgt_l, bg, zb);
    cudaEventRecord(evG, s1);

    gemm_mma<0><<<gg, 256, GEMM_SMEM, s0>>>(uh, ul, Wint_h, Wint_l, b_in, x1);
    conv_silu_kernel<<<2048, 256, 0, s0>>>(x1, convw, convb, x3, x3h, x3l);
    cudaEventRecord(evC, s0);

    cudaStreamWaitEvent(s1, evC, 0);
    proj_bc_kernel<<<MM / 32, 256, 0, s1>>>(x3, Wb, Wc, bb, bc, Bmb, Cmb);
    cudaEventRecord(evP, s1);

    gemm_mma<2><<<gg, 256, GEMM_SMEM, s0>>>(x3h, x3l, Wdtt_h, Wdtt_l, bdt, dtb);

    cudaStreamWaitEvent(s0, evG, 0);
    cudaStreamWaitEvent(s0, evP, 0);
    scan_kernel<<<BB * (DD / 8), 128, 0, s0>>>(dtb, x3, Bmb, Cmb, A, zb, yh, yl);
    gemm_mma<0><<<gg, 256, GEMM_SMEM, s0>>>(yh, yl, Wot_h, Wot_l, bout, out);
}